// round 1
// baseline (speedup 1.0000x reference)
#include <cuda_runtime.h>
#include <math.h>

#define Nn   50000
#define Ee   1000000
#define INF  256
#define Hh   4
#define Dd   64
#define OUTF 256
#define NH   (Nn * Hh)   // 200000
#define HD   (Hh * Dd)   // 256

// ---------------- scratch (device globals; no allocation allowed) ----------
__device__ float g_h[Nn * HD];      // 51.2 MB  per-node head features
__device__ float g_outh[Nn * HD];   // 51.2 MB  aggregated (un-normalized) messages
__device__ float g_ssrc[NH];        // s_src[n,h] = h[n,h,:] . a_src[h,:]
__device__ float g_sdst[NH];        // s_dst[n,h] = h[n,h,:] . a_dst[h,:]
__device__ float g_emax[NH];        // segment max per (dst, h)
__device__ float g_asum[NH];        // segment sum of alpha per (dst, h)
__device__ float g_alpha[Ee * Hh];  // 16 MB    per-edge, per-head alpha

// ---------------- init ------------------------------------------------------
__global__ void k_init() {
    int i = blockIdx.x * blockDim.x + threadIdx.x;
    int stride = gridDim.x * blockDim.x;
    float4 z = make_float4(0.f, 0.f, 0.f, 0.f);
    for (int j = i; j < (Nn * HD) / 4; j += stride)
        ((float4*)g_outh)[j] = z;
    for (int j = i; j < NH; j += stride) {
        g_asum[j] = 0.f;
        g_emax[j] = -INFINITY;
    }
}

// ---------------- SGEMM: C[M,256] = A[M,256] * B[256,256] -------------------
// wmap=1: B element (i, j) = W[h=j>>6][i][d=j&63]  (head-blocked, BN=64 aligned)
// wmap=0: B is plain row-major [256,256]
__global__ void __launch_bounds__(256) k_gemm(
    const float* __restrict__ A, const float* __restrict__ Bsrc,
    float* __restrict__ C, int M, int wmap)
{
    __shared__ float As[16][132];   // [k][m], padded row stride (132*4B = 16B mult)
    __shared__ float Bs[16][64];    // [k][n]

    const int bm = blockIdx.x * 128;
    const int bn = blockIdx.y * 64;

    const float* Bp;
    int ldb, coloff;
    if (wmap) { Bp = Bsrc + blockIdx.y * (INF * Dd); ldb = 64;  coloff = 0;  }
    else      { Bp = Bsrc;                            ldb = 256; coloff = bn; }

    const int tid = threadIdx.x;
    const int tx  = tid & 15;        // 0..15 -> 4 output cols each
    const int ty  = tid >> 4;        // 0..15 -> 8 output rows each
    const int ar  = tid >> 2;        // 0..63 A-load row (plus +64 second half)
    const int ac4 = (tid & 3) * 4;   // A-load k offset
    const int br  = tid >> 4;        // 0..15 B-load row
    const int bc  = (tid & 15) * 4;  // B-load col

    float acc[8][4];
    #pragma unroll
    for (int i = 0; i < 8; i++)
        #pragma unroll
        for (int j = 0; j < 4; j++) acc[i][j] = 0.f;

    for (int k0 = 0; k0 < 256; k0 += 16) {
        #pragma unroll
        for (int half = 0; half < 2; half++) {
            int row = bm + ar + half * 64;
            float4 v = make_float4(0.f, 0.f, 0.f, 0.f);
            if (row < M) v = *(const float4*)(A + (long)row * 256 + k0 + ac4);
            As[ac4 + 0][ar + half * 64] = v.x;
            As[ac4 + 1][ar + half * 64] = v.y;
            As[ac4 + 2][ar + half * 64] = v.z;
            As[ac4 + 3][ar + half * 64] = v.w;
        }
        {
            float4 v = *(const float4*)(Bp + (long)(k0 + br) * ldb + coloff + bc);
            *(float4*)&Bs[br][bc] = v;
        }
        __syncthreads();
        #pragma unroll
        for (int k = 0; k < 16; k++) {
            float a[8], b[4];
            #pragma unroll
            for (int i = 0; i < 8; i++) a[i] = As[k][ty * 8 + i];
            #pragma unroll
            for (int j = 0; j < 4; j++) b[j] = Bs[k][tx * 4 + j];
            #pragma unroll
            for (int i = 0; i < 8; i++)
                #pragma unroll
                for (int j = 0; j < 4; j++)
                    acc[i][j] = fmaf(a[i], b[j], acc[i][j]);
        }
        __syncthreads();
    }

    #pragma unroll
    for (int i = 0; i < 8; i++) {
        int row = bm + ty * 8 + i;
        if (row < M) {
            float4 v = make_float4(acc[i][0], acc[i][1], acc[i][2], acc[i][3]);
            *(float4*)(C + (long)row * 256 + bn + tx * 4) = v;
        }
    }
}

// ---------------- per-(node, head) attention projections --------------------
__global__ void k_scores(const float* __restrict__ attn) {
    int warp = (blockIdx.x * blockDim.x + threadIdx.x) >> 5;
    int lane = threadIdx.x & 31;
    if (warp >= NH) return;
    int n = warp >> 2, h = warp & 3;
    const float* hp = g_h + (long)n * HD + h * Dd;
    const float* ap = attn + h * 2 * Dd;
    float2 hv = *(const float2*)(hp + lane * 2);
    float2 as = *(const float2*)(ap + lane * 2);
    float2 ad = *(const float2*)(ap + Dd + lane * 2);
    float ssum = hv.x * as.x + hv.y * as.y;
    float dsum = hv.x * ad.x + hv.y * ad.y;
    #pragma unroll
    for (int o = 16; o > 0; o >>= 1) {
        ssum += __shfl_xor_sync(0xFFFFFFFFu, ssum, o);
        dsum += __shfl_xor_sync(0xFFFFFFFFu, dsum, o);
    }
    if (lane == 0) { g_ssrc[warp] = ssum; g_sdst[warp] = dsum; }
}

// ---------------- float atomic max (sign-split trick) -----------------------
__device__ __forceinline__ void atomicMaxF(float* addr, float v) {
    if (v >= 0.f) atomicMax((int*)addr, __float_as_int(v));
    else          atomicMin((unsigned int*)addr, __float_as_uint(v));
}

__device__ __forceinline__ float leaky(float v) {
    return v > 0.f ? v : 0.2f * v;
}

// ---------------- edge pass 1: segment max ----------------------------------
__global__ void k_edge_max(const int* __restrict__ ei) {
    int e = blockIdx.x * blockDim.x + threadIdx.x;
    if (e >= Ee) return;
    int s = ei[e], d = ei[Ee + e];
    float4 ss = *(const float4*)(g_ssrc + s * 4);
    float4 sd = *(const float4*)(g_sdst + d * 4);
    float sc0 = leaky(ss.x + sd.x);
    float sc1 = leaky(ss.y + sd.y);
    float sc2 = leaky(ss.z + sd.z);
    float sc3 = leaky(ss.w + sd.w);
    atomicMaxF(&g_emax[d * 4 + 0], sc0);
    atomicMaxF(&g_emax[d * 4 + 1], sc1);
    atomicMaxF(&g_emax[d * 4 + 2], sc2);
    atomicMaxF(&g_emax[d * 4 + 3], sc3);
}

// ---------------- edge pass 2: alpha + segment sum --------------------------
__global__ void k_edge_alpha(const int* __restrict__ ei) {
    int e = blockIdx.x * blockDim.x + threadIdx.x;
    if (e >= Ee) return;
    int s = ei[e], d = ei[Ee + e];
    float4 ss = *(const float4*)(g_ssrc + s * 4);
    float4 sd = *(const float4*)(g_sdst + d * 4);
    float4 em = *(const float4*)(g_emax + d * 4);
    float sc[4] = { leaky(ss.x + sd.x), leaky(ss.y + sd.y),
                    leaky(ss.z + sd.z), leaky(ss.w + sd.w) };
    float emv[4] = { em.x, em.y, em.z, em.w };
    float al[4];
    #pragma unroll
    for (int h = 0; h < 4; h++) {
        float t = fminf(sc[h] - emv[h], 20.f);
        al[h] = __expf(t);
        atomicAdd(&g_asum[d * 4 + h], al[h]);
    }
    *(float4*)(g_alpha + (long)e * 4) = make_float4(al[0], al[1], al[2], al[3]);
}

// ---------------- message scatter: out_h[dst] += alpha * h[src] -------------
// 64 threads per edge, one float4 per thread, vector reduction to gmem.
__global__ void __launch_bounds__(256) k_scatter(const int* __restrict__ ei) {
    long t = (long)blockIdx.x * blockDim.x + threadIdx.x;
    int e = (int)(t >> 6);
    int j = (int)(t & 63);          // float4 index within 256-float row
    if (e >= Ee) return;
    int s = ei[e], d = ei[Ee + e];
    int h = j >> 4;                 // 16 float4s per head
    float a = g_alpha[(long)e * 4 + h];
    float4 hv = *(const float4*)(g_h + (long)s * HD + j * 4);
    float* dst = g_outh + (long)d * HD + j * 4;
    asm volatile("red.global.add.v4.f32 [%0], {%1, %2, %3, %4};"
                 :: "l"(dst), "f"(a * hv.x), "f"(a * hv.y),
                    "f"(a * hv.z), "f"(a * hv.w)
                 : "memory");
}

// ---------------- normalize out_h by alpha_sum ------------------------------
__global__ void k_norm() {
    int t = blockIdx.x * blockDim.x + threadIdx.x;   // per float4
    if (t >= Nn * 64) return;
    int n = t >> 6, j = t & 63, h = j >> 4;
    float inv = 1.f / (g_asum[n * 4 + h] + 1e-8f);
    float4 v = ((float4*)g_outh)[t];
    v.x *= inv; v.y *= inv; v.z *= inv; v.w *= inv;
    ((float4*)g_outh)[t] = v;
}

// ---------------- launch ----------------------------------------------------
extern "C" void kernel_launch(void* const* d_in, const int* in_sizes, int n_in,
                              void* d_out, int out_size)
{
    const float* x    = (const float*)d_in[0];
    const int*   ei   = (const int*)  d_in[1];
    const float* W    = (const float*)d_in[2];
    const float* attn = (const float*)d_in[3];
    const float* Wout = (const float*)d_in[4];
    float*       out  = (float*)d_out;

    void *p_h = nullptr, *p_outh = nullptr;
    cudaGetSymbolAddress(&p_h, g_h);
    cudaGetSymbolAddress(&p_outh, g_outh);

    k_init<<<1024, 256>>>();

    dim3 gg((Nn + 127) / 128, 4);
    k_gemm<<<gg, 256>>>(x, W, (float*)p_h, Nn, 1);

    k_scores<<<(NH * 32 + 255) / 256, 256>>>(attn);

    int eb = (Ee + 255) / 256;
    k_edge_max<<<eb, 256>>>(ei);
    k_edge_alpha<<<eb, 256>>>(ei);

    k_scatter<<<(int)(((long)Ee * 64) / 256), 256>>>(ei);

    k_norm<<<(Nn * 64 + 255) / 256, 256>>>();

    k_gemm<<<gg, 256>>>((const float*)p_outh, Wout, out, Nn, 0);
}

// round 4
// speedup vs baseline: 1.3616x; 1.3616x over previous
#include <cuda_runtime.h>
#include <cuda_bf16.h>
#include <math.h>
#include <stdint.h>

#define Nn   50000
#define Ee   1000000
#define Hh   4
#define Dd   64
#define NH   (Nn * Hh)   // 200000
#define HD   (Hh * Dd)   // 256
#define KK   768         // split-bf16 packed K: [Ah|Ah|Al] . [Bh|Bl|Bh]

// ---------------- scratch (device globals; no allocation allowed) ----------
__device__ float g_h[Nn * HD];      // per-node head features (fp32)
__device__ float g_outh[Nn * HD];   // aggregated (un-normalized) messages
__device__ float g_ssrc[NH];
__device__ float g_sdst[NH];
__device__ float g_emax[NH];
__device__ float g_asum[NH];
__device__ float g_alpha[Ee * Hh];
// packed split-bf16 operands (K=768)
__device__ __nv_bfloat16 g_a2[Nn * KK];    // [xh | xh | xl]
__device__ __nv_bfloat16 g_o2[Nn * KK];    // normalized out_h packed
__device__ __nv_bfloat16 g_b1[256 * KK];   // W  head-blocked, [Bh|Bl|Bh], row n = out col
__device__ __nv_bfloat16 g_b2[256 * KK];   // W_out transposed, [Bh|Bl|Bh]

#define SWZ(o) ((o) ^ (((o) >> 3) & 0x70))

__device__ __forceinline__ uint32_t smem_u32(const void* p) {
    uint32_t a;
    asm("{ .reg .u64 t; cvta.to.shared.u64 t, %1; cvt.u32.u64 %0, t; }"
        : "=r"(a) : "l"(p));
    return a;
}
__device__ __forceinline__ void cp16(uint32_t dst, const void* src) {
    asm volatile("cp.async.cg.shared.global [%0], [%1], 16;"
                 :: "r"(dst), "l"(src) : "memory");
}
__device__ __forceinline__ void ldm_x4(uint32_t* r, uint32_t addr) {
    asm volatile("ldmatrix.sync.aligned.m8n8.x4.shared.b16 {%0,%1,%2,%3}, [%4];"
                 : "=r"(r[0]), "=r"(r[1]), "=r"(r[2]), "=r"(r[3]) : "r"(addr));
}
__device__ __forceinline__ void mma16816(float* c, const uint32_t* a,
                                         uint32_t b0, uint32_t b1) {
    asm volatile(
        "mma.sync.aligned.m16n8k16.row.col.f32.bf16.bf16.f32 "
        "{%0,%1,%2,%3}, {%4,%5,%6,%7}, {%8,%9}, {%0,%1,%2,%3};"
        : "+f"(c[0]), "+f"(c[1]), "+f"(c[2]), "+f"(c[3])
        : "r"(a[0]), "r"(a[1]), "r"(a[2]), "r"(a[3]), "r"(b0), "r"(b1));
}

// ---------------- init ------------------------------------------------------
__global__ void k_init() {
    int i = blockIdx.x * blockDim.x + threadIdx.x;
    int stride = gridDim.x * blockDim.x;
    float4 z = make_float4(0.f, 0.f, 0.f, 0.f);
    for (int j = i; j < (Nn * HD) / 4; j += stride)
        ((float4*)g_outh)[j] = z;
    for (int j = i; j < NH; j += stride) {
        g_asum[j] = 0.f;
        g_emax[j] = -INFINITY;
    }
}

// ---------------- weight prep: transpose + split-bf16 pack ------------------
__global__ void k_prep_w(const float* __restrict__ W, const float* __restrict__ Wout) {
    int t = blockIdx.x * 256 + threadIdx.x;   // 65536
    int n = t >> 8, k = t & 255;
    // W[h][k][d], out col n = h*64+d  ->  B1 row n, K-major
    float v1 = W[(((n >> 6) * 256) + k) * 64 + (n & 63)];
    __nv_bfloat16 h1 = __float2bfloat16(v1);
    __nv_bfloat16 l1 = __float2bfloat16(v1 - __bfloat162float(h1));
    g_b1[n * KK + k]       = h1;
    g_b1[n * KK + 256 + k] = l1;
    g_b1[n * KK + 512 + k] = h1;
    // Wout[k][n] -> B2 row n
    float v2 = Wout[k * 256 + n];
    __nv_bfloat16 h2 = __float2bfloat16(v2);
    __nv_bfloat16 l2 = __float2bfloat16(v2 - __bfloat162float(h2));
    g_b2[n * KK + k]       = h2;
    g_b2[n * KK + 256 + k] = l2;
    g_b2[n * KK + 512 + k] = h2;
}

// ---------------- pack fp32 row-major [M,256] -> [hi|hi|lo] bf16 ------------
__device__ __forceinline__ void pack_split(const float* f, uint2& ph, uint2& pl) {
    unsigned short hs[4], ls[4];
#pragma unroll
    for (int i = 0; i < 4; i++) {
        __nv_bfloat16 h = __float2bfloat16(f[i]);
        __nv_bfloat16 l = __float2bfloat16(f[i] - __bfloat162float(h));
        hs[i] = __bfloat16_as_ushort(h);
        ls[i] = __bfloat16_as_ushort(l);
    }
    ph = make_uint2((uint32_t)hs[0] | ((uint32_t)hs[1] << 16),
                    (uint32_t)hs[2] | ((uint32_t)hs[3] << 16));
    pl = make_uint2((uint32_t)ls[0] | ((uint32_t)ls[1] << 16),
                    (uint32_t)ls[2] | ((uint32_t)ls[3] << 16));
}

__global__ void k_prep_x(const float* __restrict__ x) {
    int t = blockIdx.x * blockDim.x + threadIdx.x;   // per float4
    if (t >= Nn * 64) return;
    float4 v = ((const float4*)x)[t];
    float f[4] = { v.x, v.y, v.z, v.w };
    uint2 ph, pl;
    pack_split(f, ph, pl);
    long base = (long)(t >> 6) * KK + (t & 63) * 4;
    *(uint2*)(g_a2 + base)       = ph;
    *(uint2*)(g_a2 + base + 256) = ph;
    *(uint2*)(g_a2 + base + 512) = pl;
}

// ---------------- bf16 mma.sync GEMM: C[M,256] = A2[M,768] * B2[256,768]^T --
// CTA 128x128, 8 warps (2x4), warp tile 64x32, K-chunk 64, 2-stage cp.async.
__global__ void __launch_bounds__(256) k_gemm_mma(
    const __nv_bfloat16* __restrict__ A, const __nv_bfloat16* __restrict__ B,
    float* __restrict__ C, int M)
{
    extern __shared__ char sm[];                    // 2 x (16KB A + 16KB B)
    uint32_t sbase = smem_u32(sm);
    const int tid = threadIdx.x;
    const int wid = tid >> 5, lid = tid & 31;
    const int bm = blockIdx.x * 128, bn = blockIdx.y * 128;
    const int wm = (wid >> 2) * 64, wn = (wid & 3) * 32;

    // A ldmatrix lane addressing (16x16 tile): 4 8x8 quads
    const int arow = (lid & 7) + ((lid >> 3) & 1) * 8;
    const int acol = (lid >> 4) * 8;
    // B ldmatrix lane addressing (16 n-rows x 16 k): quads n0k0,n0k8,n8k0,n8k8
    const int q = lid >> 3;
    const int brow = (lid & 7) + (q >> 1) * 8;
    const int bcol = (q & 1) * 8;

    float acc[4][4][4];
#pragma unroll
    for (int mi = 0; mi < 4; mi++)
#pragma unroll
        for (int ni = 0; ni < 4; ni++)
#pragma unroll
            for (int j = 0; j < 4; j++) acc[mi][ni][j] = 0.f;

    // chunk loader: 128x64 A + 128x64 B, 16B per thread x 4 iters each
    auto load_chunk = [&](int c, int s) {
        uint32_t abase = sbase + s * 32768;
#pragma unroll
        for (int it = 0; it < 4; it++) {
            int idx = tid + it * 256;            // 0..1023
            int row = idx >> 3, col = (idx & 7) * 8;
            long ar = bm + row; if (ar >= M) ar = M - 1;
            cp16(abase + SWZ(row * 128 + col * 2), A + ar * KK + c * 64 + col);
        }
#pragma unroll
        for (int it = 0; it < 4; it++) {
            int idx = tid + it * 256;
            int row = idx >> 3, col = (idx & 7) * 8;
            cp16(abase + 16384 + SWZ(row * 128 + col * 2),
                 B + (long)(bn + row) * KK + c * 64 + col);
        }
        asm volatile("cp.async.commit_group;" ::: "memory");
    };

    auto compute_chunk = [&](int s) {
        uint32_t abase = sbase + s * 32768;
        uint32_t bbase = abase + 16384;
#pragma unroll
        for (int ks = 0; ks < 4; ks++) {
            uint32_t a[4][4];
#pragma unroll
            for (int mi = 0; mi < 4; mi++)
                ldm_x4(a[mi], abase + SWZ((wm + mi * 16 + arow) * 128 +
                                          (ks * 16 + acol) * 2));
            uint32_t b[2][4];
#pragma unroll
            for (int nj = 0; nj < 2; nj++)
                ldm_x4(b[nj], bbase + SWZ((wn + nj * 16 + brow) * 128 +
                                          (ks * 16 + bcol) * 2));
#pragma unroll
            for (int mi = 0; mi < 4; mi++)
#pragma unroll
                for (int ni = 0; ni < 4; ni++)
                    mma16816(acc[mi][ni], a[mi],
                             b[ni >> 1][(ni & 1) * 2], b[ni >> 1][(ni & 1) * 2 + 1]);
        }
    };

    load_chunk(0, 0);
    const int NC = KK / 64;                      // 12
    for (int c = 0; c < NC; c++) {
        if (c + 1 < NC) {
            load_chunk(c + 1, (c + 1) & 1);
            asm volatile("cp.async.wait_group 1;" ::: "memory");
        } else {
            asm volatile("cp.async.wait_group 0;" ::: "memory");
        }
        __syncthreads();
        compute_chunk(c & 1);
        __syncthreads();
    }

    // epilogue
    const int g = lid >> 2, tig = lid & 3;
#pragma unroll
    for (int mi = 0; mi < 4; mi++) {
        int r0 = bm + wm + mi * 16 + g;
#pragma unroll
        for (int ni = 0; ni < 4; ni++) {
            int col = bn + wn + ni * 8 + tig * 2;
            if (r0 < M)
                *(float2*)(C + (long)r0 * 256 + col) =
                    make_float2(acc[mi][ni][0], acc[mi][ni][1]);
            if (r0 + 8 < M)
                *(float2*)(C + (long)(r0 + 8) * 256 + col) =
                    make_float2(acc[mi][ni][2], acc[mi][ni][3]);
        }
    }
}

// ---------------- per-(node, head) attention projections --------------------
__global__ void k_scores(const float* __restrict__ attn) {
    int warp = (blockIdx.x * blockDim.x + threadIdx.x) >> 5;
    int lane = threadIdx.x & 31;
    if (warp >= NH) return;
    int n = warp >> 2, h = warp & 3;
    const float* hp = g_h + (long)n * HD + h * Dd;
    const float* ap = attn + h * 2 * Dd;
    float2 hv = *(const float2*)(hp + lane * 2);
    float2 as = *(const float2*)(ap + lane * 2);
    float2 ad = *(const float2*)(ap + Dd + lane * 2);
    float ssum = hv.x * as.x + hv.y * as.y;
    float dsum = hv.x * ad.x + hv.y * ad.y;
#pragma unroll
    for (int o = 16; o > 0; o >>= 1) {
        ssum += __shfl_xor_sync(0xFFFFFFFFu, ssum, o);
        dsum += __shfl_xor_sync(0xFFFFFFFFu, dsum, o);
    }
    if (lane == 0) { g_ssrc[warp] = ssum; g_sdst[warp] = dsum; }
}

// ---------------- float atomic max (sign-split trick) -----------------------
__device__ __forceinline__ void atomicMaxF(float* addr, float v) {
    if (v >= 0.f) atomicMax((int*)addr, __float_as_int(v));
    else          atomicMin((unsigned int*)addr, __float_as_uint(v));
}

__device__ __forceinline__ float leaky(float v) {
    return v > 0.f ? v : 0.2f * v;
}

// ---------------- edge pass 1: segment max ----------------------------------
__global__ void k_edge_max(const int* __restrict__ ei) {
    int e = blockIdx.x * blockDim.x + threadIdx.x;
    if (e >= Ee) return;
    int s = ei[e], d = ei[Ee + e];
    float4 ss = *(const float4*)(g_ssrc + s * 4);
    float4 sd = *(const float4*)(g_sdst + d * 4);
    atomicMaxF(&g_emax[d * 4 + 0], leaky(ss.x + sd.x));
    atomicMaxF(&g_emax[d * 4 + 1], leaky(ss.y + sd.y));
    atomicMaxF(&g_emax[d * 4 + 2], leaky(ss.z + sd.z));
    atomicMaxF(&g_emax[d * 4 + 3], leaky(ss.w + sd.w));
}

// ---------------- edge pass 2: alpha + segment sum --------------------------
__global__ void k_edge_alpha(const int* __restrict__ ei) {
    int e = blockIdx.x * blockDim.x + threadIdx.x;
    if (e >= Ee) return;
    int s = ei[e], d = ei[Ee + e];
    float4 ss = *(const float4*)(g_ssrc + s * 4);
    float4 sd = *(const float4*)(g_sdst + d * 4);
    float4 em = *(const float4*)(g_emax + d * 4);
    float sc[4] = { leaky(ss.x + sd.x), leaky(ss.y + sd.y),
                    leaky(ss.z + sd.z), leaky(ss.w + sd.w) };
    float emv[4] = { em.x, em.y, em.z, em.w };
    float al[4];
#pragma unroll
    for (int h = 0; h < 4; h++) {
        float t = fminf(sc[h] - emv[h], 20.f);
        al[h] = __expf(t);
        atomicAdd(&g_asum[d * 4 + h], al[h]);
    }
    *(float4*)(g_alpha + (long)e * 4) = make_float4(al[0], al[1], al[2], al[3]);
}

// ---------------- message scatter: out_h[dst] += alpha * h[src] -------------
__global__ void __launch_bounds__(256) k_scatter(const int* __restrict__ ei) {
    long t = (long)blockIdx.x * blockDim.x + threadIdx.x;
    int e = (int)(t >> 6);
    int j = (int)(t & 63);
    if (e >= Ee) return;
    int s = ei[e], d = ei[Ee + e];
    int h = j >> 4;
    float a = g_alpha[(long)e * 4 + h];
    float4 hv = *(const float4*)(g_h + (long)s * HD + j * 4);
    float* dst = g_outh + (long)d * HD + j * 4;
    asm volatile("red.global.add.v4.f32 [%0], {%1, %2, %3, %4};"
                 :: "l"(dst), "f"(a * hv.x), "f"(a * hv.y),
                    "f"(a * hv.z), "f"(a * hv.w)
                 : "memory");
}

// ---------------- normalize + split-bf16 pack for GEMM2 ---------------------
__global__ void k_norm() {
    int t = blockIdx.x * blockDim.x + threadIdx.x;   // per float4
    if (t >= Nn * 64) return;
    int n = t >> 6, j = t & 63, h = j >> 4;
    float inv = 1.f / (g_asum[n * 4 + h] + 1e-8f);
    float4 v = ((float4*)g_outh)[t];
    float f[4] = { v.x * inv, v.y * inv, v.z * inv, v.w * inv };
    uint2 ph, pl;
    pack_split(f, ph, pl);
    long base = (long)n * KK + j * 4;
    *(uint2*)(g_o2 + base)       = ph;
    *(uint2*)(g_o2 + base + 256) = ph;
    *(uint2*)(g_o2 + base + 512) = pl;
}

// ---------------- launch ----------------------------------------------------
extern "C" void kernel_launch(void* const* d_in, const int* in_sizes, int n_in,
                              void* d_out, int out_size)
{
    const float* x    = (const float*)d_in[0];
    const int*   ei   = (const int*)  d_in[1];
    const float* W    = (const float*)d_in[2];
    const float* attn = (const float*)d_in[3];
    const float* Wout = (const float*)d_in[4];
    float*       out  = (float*)d_out;

    void *p_h, *p_a2, *p_o2, *p_b1, *p_b2;
    cudaGetSymbolAddress(&p_h, g_h);
    cudaGetSymbolAddress(&p_a2, g_a2);
    cudaGetSymbolAddress(&p_o2, g_o2);
    cudaGetSymbolAddress(&p_b1, g_b1);
    cudaGetSymbolAddress(&p_b2, g_b2);

    cudaFuncSetAttribute(k_gemm_mma, cudaFuncAttributeMaxDynamicSharedMemorySize, 65536);

    k_init<<<1024, 256>>>();
    k_prep_w<<<256, 256>>>(W, Wout);
    k_prep_x<<<(Nn * 64 + 255) / 256, 256>>>(x);

    dim3 gg((Nn + 127) / 128, 2);
    k_gemm_mma<<<gg, 256, 65536>>>((const __nv_bfloat16*)p_a2,
                                   (const __nv_bfloat16*)p_b1,
                                   (float*)p_h, Nn);

    k_scores<<<(NH * 32 + 255) / 256, 256>>>(attn);

    int eb = (Ee + 255) / 256;
    k_edge_max<<<eb, 256>>>(ei);
    k_edge_alpha<<<eb, 256>>>(ei);

    k_scatter<<<(int)(((long)Ee * 64) / 256), 256>>>(ei);

    k_norm<<<(Nn * 64 + 255) / 256, 256>>>();

    k_gemm_mma<<<gg, 256, 65536>>>((const __nv_bfloat16*)p_o2,
                                   (const __nv_bfloat16*)p_b2,
                                   out, Nn);
}

// round 5
// speedup vs baseline: 1.8553x; 1.3626x over previous
#include <cuda_runtime.h>
#include <cuda_bf16.h>
#include <math.h>
#include <stdint.h>

#define Nn   50000
#define Ee   1000000
#define Hh   4
#define Dd   64
#define NH   (Nn * Hh)   // 200000
#define HD   (Hh * Dd)   // 256
#define KK   768         // split-bf16 packed K: [Ah|Ah|Al] . [Bh|Bl|Bh]

// ---------------- scratch (device globals; no allocation allowed) ----------
__device__ float g_h[Nn * HD];      // per-node head features (fp32)
__device__ float g_ssrc[NH];        // [n][h] float4 per node
__device__ float g_sdst[NH];
// CSR (dst-bucketed) edge structures
__device__ int   g_cnt[Nn];         // in-degree
__device__ int   g_off[Nn];         // exclusive prefix of cnt
__device__ int   g_cur[Nn];         // fill cursor
__device__ int   g_srcs[Ee];        // src node per sorted slot
__device__ float g_alp[Ee * Hh];    // alpha (4 floats) per sorted slot
// packed split-bf16 operands (K=768)
__device__ __nv_bfloat16 g_a2[Nn * KK];    // [xh | xh | xl]
__device__ __nv_bfloat16 g_o2[Nn * KK];    // normalized out_h packed
__device__ __nv_bfloat16 g_b1[256 * KK];   // W  head-blocked, row n = out col
__device__ __nv_bfloat16 g_b2[256 * KK];   // W_out transposed

#define SWZ(o) ((o) ^ (((o) >> 3) & 0x70))

__device__ __forceinline__ uint32_t smem_u32(const void* p) {
    uint32_t a;
    asm("{ .reg .u64 t; cvta.to.shared.u64 t, %1; cvt.u32.u64 %0, t; }"
        : "=r"(a) : "l"(p));
    return a;
}
__device__ __forceinline__ void cp16(uint32_t dst, const void* src) {
    asm volatile("cp.async.cg.shared.global [%0], [%1], 16;"
                 :: "r"(dst), "l"(src) : "memory");
}
__device__ __forceinline__ void ldm_x4(uint32_t* r, uint32_t addr) {
    asm volatile("ldmatrix.sync.aligned.m8n8.x4.shared.b16 {%0,%1,%2,%3}, [%4];"
                 : "=r"(r[0]), "=r"(r[1]), "=r"(r[2]), "=r"(r[3]) : "r"(addr));
}
__device__ __forceinline__ void mma16816(float* c, const uint32_t* a,
                                         uint32_t b0, uint32_t b1) {
    asm volatile(
        "mma.sync.aligned.m16n8k16.row.col.f32.bf16.bf16.f32 "
        "{%0,%1,%2,%3}, {%4,%5,%6,%7}, {%8,%9}, {%0,%1,%2,%3};"
        : "+f"(c[0]), "+f"(c[1]), "+f"(c[2]), "+f"(c[3])
        : "r"(a[0]), "r"(a[1]), "r"(a[2]), "r"(a[3]), "r"(b0), "r"(b1));
}

// ---------------- CSR build -------------------------------------------------
__global__ void k_init0() {
    int i = blockIdx.x * blockDim.x + threadIdx.x;
    if (i < Nn) g_cnt[i] = 0;
}
__global__ void k_hist(const int* __restrict__ ei) {
    int e = blockIdx.x * blockDim.x + threadIdx.x;
    if (e < Ee) atomicAdd(&g_cnt[ei[Ee + e]], 1);
}
// single-block exclusive scan over 50000 counts (1024 threads x 49 each)
__global__ void __launch_bounds__(1024) k_scan() {
    __shared__ int ts[1024];
    const int C = (Nn + 1023) / 1024;   // 49
    int tid = threadIdx.x;
    int beg = tid * C, end = min(beg + C, Nn);
    int sum = 0;
    for (int i = beg; i < end; i++) sum += g_cnt[i];
    ts[tid] = sum;
    __syncthreads();
    // Hillis-Steele inclusive scan on thread totals
    for (int o = 1; o < 1024; o <<= 1) {
        int v = (tid >= o) ? ts[tid - o] : 0;
        __syncthreads();
        ts[tid] += v;
        __syncthreads();
    }
    int run = (tid > 0) ? ts[tid - 1] : 0;   // exclusive base for this chunk
    for (int i = beg; i < end; i++) {
        int c = g_cnt[i];
        g_off[i] = run;
        g_cur[i] = run;
        run += c;
    }
}

// ---------------- weight prep: transpose + split-bf16 pack ------------------
__global__ void k_prep_w(const float* __restrict__ W, const float* __restrict__ Wout) {
    int t = blockIdx.x * 256 + threadIdx.x;   // 65536
    int n = t >> 8, k = t & 255;
    float v1 = W[(((n >> 6) * 256) + k) * 64 + (n & 63)];
    __nv_bfloat16 h1 = __float2bfloat16(v1);
    __nv_bfloat16 l1 = __float2bfloat16(v1 - __bfloat162float(h1));
    g_b1[n * KK + k]       = h1;
    g_b1[n * KK + 256 + k] = l1;
    g_b1[n * KK + 512 + k] = h1;
    float v2 = Wout[k * 256 + n];
    __nv_bfloat16 h2 = __float2bfloat16(v2);
    __nv_bfloat16 l2 = __float2bfloat16(v2 - __bfloat162float(h2));
    g_b2[n * KK + k]       = h2;
    g_b2[n * KK + 256 + k] = l2;
    g_b2[n * KK + 512 + k] = h2;
}

// ---------------- pack fp32 -> [hi|hi|lo] bf16 helpers ----------------------
__device__ __forceinline__ void pack_split(const float* f, uint2& ph, uint2& pl) {
    unsigned short hs[4], ls[4];
#pragma unroll
    for (int i = 0; i < 4; i++) {
        __nv_bfloat16 h = __float2bfloat16(f[i]);
        __nv_bfloat16 l = __float2bfloat16(f[i] - __bfloat162float(h));
        hs[i] = __bfloat16_as_ushort(h);
        ls[i] = __bfloat16_as_ushort(l);
    }
    ph = make_uint2((uint32_t)hs[0] | ((uint32_t)hs[1] << 16),
                    (uint32_t)hs[2] | ((uint32_t)hs[3] << 16));
    pl = make_uint2((uint32_t)ls[0] | ((uint32_t)ls[1] << 16),
                    (uint32_t)ls[2] | ((uint32_t)ls[3] << 16));
}

__global__ void k_prep_x(const float* __restrict__ x) {
    int t = blockIdx.x * blockDim.x + threadIdx.x;   // per float4
    if (t >= Nn * 64) return;
    float4 v = ((const float4*)x)[t];
    float f[4] = { v.x, v.y, v.z, v.w };
    uint2 ph, pl;
    pack_split(f, ph, pl);
    long base = (long)(t >> 6) * KK + (t & 63) * 4;
    *(uint2*)(g_a2 + base)       = ph;
    *(uint2*)(g_a2 + base + 256) = ph;
    *(uint2*)(g_a2 + base + 512) = pl;
}

// ---------------- bf16 mma.sync GEMM: C[M,256] = A2[M,768] * B2[256,768]^T --
__global__ void __launch_bounds__(256) k_gemm_mma(
    const __nv_bfloat16* __restrict__ A, const __nv_bfloat16* __restrict__ B,
    float* __restrict__ C, int M)
{
    extern __shared__ char sm[];
    uint32_t sbase = smem_u32(sm);
    const int tid = threadIdx.x;
    const int wid = tid >> 5, lid = tid & 31;
    const int bm = blockIdx.x * 128, bn = blockIdx.y * 128;
    const int wm = (wid >> 2) * 64, wn = (wid & 3) * 32;

    const int arow = (lid & 7) + ((lid >> 3) & 1) * 8;
    const int acol = (lid >> 4) * 8;
    const int q = lid >> 3;
    const int brow = (lid & 7) + (q >> 1) * 8;
    const int bcol = (q & 1) * 8;

    float acc[4][4][4];
#pragma unroll
    for (int mi = 0; mi < 4; mi++)
#pragma unroll
        for (int ni = 0; ni < 4; ni++)
#pragma unroll
            for (int j = 0; j < 4; j++) acc[mi][ni][j] = 0.f;

    auto load_chunk = [&](int c, int s) {
        uint32_t abase = sbase + s * 32768;
#pragma unroll
        for (int it = 0; it < 4; it++) {
            int idx = tid + it * 256;
            int row = idx >> 3, col = (idx & 7) * 8;
            long ar = bm + row; if (ar >= M) ar = M - 1;
            cp16(abase + SWZ(row * 128 + col * 2), A + ar * KK + c * 64 + col);
        }
#pragma unroll
        for (int it = 0; it < 4; it++) {
            int idx = tid + it * 256;
            int row = idx >> 3, col = (idx & 7) * 8;
            cp16(abase + 16384 + SWZ(row * 128 + col * 2),
                 B + (long)(bn + row) * KK + c * 64 + col);
        }
        asm volatile("cp.async.commit_group;" ::: "memory");
    };

    auto compute_chunk = [&](int s) {
        uint32_t abase = sbase + s * 32768;
        uint32_t bbase = abase + 16384;
#pragma unroll
        for (int ks = 0; ks < 4; ks++) {
            uint32_t a[4][4];
#pragma unroll
            for (int mi = 0; mi < 4; mi++)
                ldm_x4(a[mi], abase + SWZ((wm + mi * 16 + arow) * 128 +
                                          (ks * 16 + acol) * 2));
            uint32_t b[2][4];
#pragma unroll
            for (int nj = 0; nj < 2; nj++)
                ldm_x4(b[nj], bbase + SWZ((wn + nj * 16 + brow) * 128 +
                                          (ks * 16 + bcol) * 2));
#pragma unroll
            for (int mi = 0; mi < 4; mi++)
#pragma unroll
                for (int ni = 0; ni < 4; ni++)
                    mma16816(acc[mi][ni], a[mi],
                             b[ni >> 1][(ni & 1) * 2], b[ni >> 1][(ni & 1) * 2 + 1]);
        }
    };

    load_chunk(0, 0);
    const int NC = KK / 64;                      // 12
    for (int c = 0; c < NC; c++) {
        if (c + 1 < NC) {
            load_chunk(c + 1, (c + 1) & 1);
            asm volatile("cp.async.wait_group 1;" ::: "memory");
        } else {
            asm volatile("cp.async.wait_group 0;" ::: "memory");
        }
        __syncthreads();
        compute_chunk(c & 1);
        __syncthreads();
    }

    const int g = lid >> 2, tig = lid & 3;
#pragma unroll
    for (int mi = 0; mi < 4; mi++) {
        int r0 = bm + wm + mi * 16 + g;
#pragma unroll
        for (int ni = 0; ni < 4; ni++) {
            int col = bn + wn + ni * 8 + tig * 2;
            if (r0 < M)
                *(float2*)(C + (long)r0 * 256 + col) =
                    make_float2(acc[mi][ni][0], acc[mi][ni][1]);
            if (r0 + 8 < M)
                *(float2*)(C + (long)(r0 + 8) * 256 + col) =
                    make_float2(acc[mi][ni][2], acc[mi][ni][3]);
        }
    }
}

// ---------------- per-(node, head) attention projections --------------------
__global__ void k_scores(const float* __restrict__ attn) {
    int warp = (blockIdx.x * blockDim.x + threadIdx.x) >> 5;
    int lane = threadIdx.x & 31;
    if (warp >= NH) return;
    int n = warp >> 2, h = warp & 3;
    const float* hp = g_h + (long)n * HD + h * Dd;
    const float* ap = attn + h * 2 * Dd;
    float2 hv = *(const float2*)(hp + lane * 2);
    float2 as = *(const float2*)(ap + lane * 2);
    float2 ad = *(const float2*)(ap + Dd + lane * 2);
    float ssum = hv.x * as.x + hv.y * as.y;
    float dsum = hv.x * ad.x + hv.y * ad.y;
#pragma unroll
    for (int o = 16; o > 0; o >>= 1) {
        ssum += __shfl_xor_sync(0xFFFFFFFFu, ssum, o);
        dsum += __shfl_xor_sync(0xFFFFFFFFu, dsum, o);
    }
    if (lane == 0) { g_ssrc[warp] = ssum; g_sdst[warp] = dsum; }
}

__device__ __forceinline__ float leaky(float v) {
    return v > 0.f ? v : 0.2f * v;
}

// ---------------- edge pass: alpha = exp(leaky(e)), bucket into CSR ---------
// No segment-max needed: exp(e)/sum(exp(e)) == exp(e-max)/sum(exp(e-max)),
// and the min(.,20) clip never binds since e - max <= 0 in the reference.
__global__ void k_edge_sort(const int* __restrict__ ei) {
    int e = blockIdx.x * blockDim.x + threadIdx.x;
    if (e >= Ee) return;
    int s = ei[e], d = ei[Ee + e];
    float4 ss = *(const float4*)(g_ssrc + s * 4);
    float4 sd = *(const float4*)(g_sdst + d * 4);
    float4 al;
    al.x = __expf(leaky(ss.x + sd.x));
    al.y = __expf(leaky(ss.y + sd.y));
    al.z = __expf(leaky(ss.z + sd.z));
    al.w = __expf(leaky(ss.w + sd.w));
    int pos = atomicAdd(&g_cur[d], 1);
    g_srcs[pos] = s;
    *(float4*)(g_alp + (long)pos * 4) = al;
}

// ---------------- gather aggregation + normalize + split-bf16 pack ----------
// 64 threads per dst node (4 nodes per 256-thread block). No atomics.
__global__ void __launch_bounds__(256) k_agg() {
    int d = blockIdx.x * 4 + (threadIdx.x >> 6);
    if (d >= Nn) return;
    int j = threadIdx.x & 63;        // float4 index within 256-float row
    int h = j >> 4;
    int beg = g_off[d], cnt = g_cnt[d];
    float4 acc = make_float4(0.f, 0.f, 0.f, 0.f);
    float asum = 0.f;
    for (int k = beg; k < beg + cnt; k++) {
        int s = g_srcs[k];
        float a = g_alp[(long)k * 4 + h];
        float4 hv = *(const float4*)(g_h + (long)s * HD + j * 4);
        asum += a;
        acc.x = fmaf(a, hv.x, acc.x);
        acc.y = fmaf(a, hv.y, acc.y);
        acc.z = fmaf(a, hv.z, acc.z);
        acc.w = fmaf(a, hv.w, acc.w);
    }
    float inv = 1.f / (asum + 1e-8f);
    float f[4] = { acc.x * inv, acc.y * inv, acc.z * inv, acc.w * inv };
    uint2 ph, pl;
    pack_split(f, ph, pl);
    long base = (long)d * KK + j * 4;
    *(uint2*)(g_o2 + base)       = ph;
    *(uint2*)(g_o2 + base + 256) = ph;
    *(uint2*)(g_o2 + base + 512) = pl;
}

// ---------------- launch ----------------------------------------------------
extern "C" void kernel_launch(void* const* d_in, const int* in_sizes, int n_in,
                              void* d_out, int out_size)
{
    const float* x    = (const float*)d_in[0];
    const int*   ei   = (const int*)  d_in[1];
    const float* W    = (const float*)d_in[2];
    const float* attn = (const float*)d_in[3];
    const float* Wout = (const float*)d_in[4];
    float*       out  = (float*)d_out;

    void *p_h, *p_a2, *p_o2, *p_b1, *p_b2;
    cudaGetSymbolAddress(&p_h, g_h);
    cudaGetSymbolAddress(&p_a2, g_a2);
    cudaGetSymbolAddress(&p_o2, g_o2);
    cudaGetSymbolAddress(&p_b1, g_b1);
    cudaGetSymbolAddress(&p_b2, g_b2);

    cudaFuncSetAttribute(k_gemm_mma, cudaFuncAttributeMaxDynamicSharedMemorySize, 65536);

    int eb = (Ee + 255) / 256;

    k_init0<<<(Nn + 255) / 256, 256>>>();
    k_hist<<<eb, 256>>>(ei);
    k_scan<<<1, 1024>>>();
    k_prep_w<<<256, 256>>>(W, Wout);
    k_prep_x<<<(Nn * 64 + 255) / 256, 256>>>(x);

    dim3 gg((Nn + 127) / 128, 2);
    k_gemm_mma<<<gg, 256, 65536>>>((const __nv_bfloat16*)p_a2,
                                   (const __nv_bfloat16*)p_b1,
                                   (float*)p_h, Nn);

    k_scores<<<(NH * 32 + 255) / 256, 256>>>(attn);

    k_edge_sort<<<eb, 256>>>(ei);

    k_agg<<<(Nn + 3) / 4, 256>>>();

    k_gemm_mma<<<gg, 256, 65536>>>((const __nv_bfloat16*)p_o2,
                                   (const __nv_bfloat16*)p_b2,
                                   out, Nn);
}

// round 6
// speedup vs baseline: 1.8945x; 1.0211x over previous
#include <cuda_runtime.h>
#include <cuda_bf16.h>
#include <cuda_fp16.h>
#include <math.h>
#include <stdint.h>

#define Nn   50000
#define Ee   1000000
#define Hh   4
#define Dd   64
#define NH   (Nn * Hh)   // 200000
#define HD   (Hh * Dd)   // 256
#define KA   512         // A storage: [Ah | Al]
#define KK   768         // B storage: [Bh | Bl | Bh]; virtual GEMM K

// ---------------- scratch (device globals; no allocation allowed) ----------
__device__ float  g_h[Nn * HD];     // per-node head features (fp32, for scores)
__device__ __half g_hf[Nn * HD];    // fp16 copy for the gather pass
__device__ float  g_ssrc[NH];
__device__ float  g_sdst[NH];
// CSR (dst-bucketed) edge structures
__device__ int    g_cnt[Nn];
__device__ int    g_off[Nn];
__device__ int    g_cur[Nn];
__device__ int    g_srcs[Ee];
__device__ float  g_alp[Ee * Hh];
// packed split-bf16 operands
__device__ __nv_bfloat16 g_a2[Nn * KA];    // [xh | xl]
__device__ __nv_bfloat16 g_o2[Nn * KA];    // normalized out_h packed [hi | lo]
__device__ __nv_bfloat16 g_b1[256 * KK];   // W  head-blocked, row n = out col
__device__ __nv_bfloat16 g_b2[256 * KK];   // W_out transposed

#define SWZ(o) ((o) ^ (((o) >> 3) & 0x70))

__device__ __forceinline__ uint32_t smem_u32(const void* p) {
    uint32_t a;
    asm("{ .reg .u64 t; cvta.to.shared.u64 t, %1; cvt.u32.u64 %0, t; }"
        : "=r"(a) : "l"(p));
    return a;
}
__device__ __forceinline__ void cp16(uint32_t dst, const void* src) {
    asm volatile("cp.async.cg.shared.global [%0], [%1], 16;"
                 :: "r"(dst), "l"(src) : "memory");
}
__device__ __forceinline__ void ldm_x4(uint32_t* r, uint32_t addr) {
    asm volatile("ldmatrix.sync.aligned.m8n8.x4.shared.b16 {%0,%1,%2,%3}, [%4];"
                 : "=r"(r[0]), "=r"(r[1]), "=r"(r[2]), "=r"(r[3]) : "r"(addr));
}
__device__ __forceinline__ void mma16816(float* c, const uint32_t* a,
                                         uint32_t b0, uint32_t b1) {
    asm volatile(
        "mma.sync.aligned.m16n8k16.row.col.f32.bf16.bf16.f32 "
        "{%0,%1,%2,%3}, {%4,%5,%6,%7}, {%8,%9}, {%0,%1,%2,%3};"
        : "+f"(c[0]), "+f"(c[1]), "+f"(c[2]), "+f"(c[3])
        : "r"(a[0]), "r"(a[1]), "r"(a[2]), "r"(a[3]), "r"(b0), "r"(b1));
}

// ---------------- CSR build -------------------------------------------------
__global__ void k_init0() {
    int i = blockIdx.x * blockDim.x + threadIdx.x;
    if (i < Nn) g_cnt[i] = 0;
}
__global__ void k_hist(const int* __restrict__ ei) {
    int e = blockIdx.x * blockDim.x + threadIdx.x;
    if (e < Ee) atomicAdd(&g_cnt[ei[Ee + e]], 1);
}
__global__ void __launch_bounds__(1024) k_scan() {
    __shared__ int ts[1024];
    const int C = (Nn + 1023) / 1024;   // 49
    int tid = threadIdx.x;
    int beg = tid * C, end = min(beg + C, Nn);
    int sum = 0;
    for (int i = beg; i < end; i++) sum += g_cnt[i];
    ts[tid] = sum;
    __syncthreads();
    for (int o = 1; o < 1024; o <<= 1) {
        int v = (tid >= o) ? ts[tid - o] : 0;
        __syncthreads();
        ts[tid] += v;
        __syncthreads();
    }
    int run = (tid > 0) ? ts[tid - 1] : 0;
    for (int i = beg; i < end; i++) {
        int c = g_cnt[i];
        g_off[i] = run;
        g_cur[i] = run;
        run += c;
    }
}

// ---------------- weight prep: transpose + split-bf16 pack ------------------
__global__ void k_prep_w(const float* __restrict__ W, const float* __restrict__ Wout) {
    int t = blockIdx.x * 256 + threadIdx.x;   // 65536
    int n = t >> 8, k = t & 255;
    float v1 = W[(((n >> 6) * 256) + k) * 64 + (n & 63)];
    __nv_bfloat16 h1 = __float2bfloat16(v1);
    __nv_bfloat16 l1 = __float2bfloat16(v1 - __bfloat162float(h1));
    g_b1[n * KK + k]       = h1;
    g_b1[n * KK + 256 + k] = l1;
    g_b1[n * KK + 512 + k] = h1;
    float v2 = Wout[k * 256 + n];
    __nv_bfloat16 h2 = __float2bfloat16(v2);
    __nv_bfloat16 l2 = __float2bfloat16(v2 - __bfloat162float(h2));
    g_b2[n * KK + k]       = h2;
    g_b2[n * KK + 256 + k] = l2;
    g_b2[n * KK + 512 + k] = h2;
}

// ---------------- pack fp32 -> [hi | lo] bf16 -------------------------------
__device__ __forceinline__ void pack_split(const float* f, uint2& ph, uint2& pl) {
    unsigned short hs[4], ls[4];
#pragma unroll
    for (int i = 0; i < 4; i++) {
        __nv_bfloat16 h = __float2bfloat16(f[i]);
        __nv_bfloat16 l = __float2bfloat16(f[i] - __bfloat162float(h));
        hs[i] = __bfloat16_as_ushort(h);
        ls[i] = __bfloat16_as_ushort(l);
    }
    ph = make_uint2((uint32_t)hs[0] | ((uint32_t)hs[1] << 16),
                    (uint32_t)hs[2] | ((uint32_t)hs[3] << 16));
    pl = make_uint2((uint32_t)ls[0] | ((uint32_t)ls[1] << 16),
                    (uint32_t)ls[2] | ((uint32_t)ls[3] << 16));
}

__global__ void k_prep_x(const float* __restrict__ x) {
    int t = blockIdx.x * blockDim.x + threadIdx.x;   // per float4
    if (t >= Nn * 64) return;
    float4 v = ((const float4*)x)[t];
    float f[4] = { v.x, v.y, v.z, v.w };
    uint2 ph, pl;
    pack_split(f, ph, pl);
    long base = (long)(t >> 6) * KA + (t & 63) * 4;
    *(uint2*)(g_a2 + base)       = ph;
    *(uint2*)(g_a2 + base + 256) = pl;
}

// ---------------- bf16 mma.sync GEMM ----------------------------------------
// C[M,256] = A[M,512:(hi|lo)] x B[256,768:(Bh|Bl|Bh)]^T over virtual K=768:
// chunk c in [0,12): A k-off = (c&3)*64 + (c>=8 ? 256 : 0); B k-off = c*64.
// grid = (2 n-tiles, 391 m-tiles) so n-tile pairs share A via L2.
// If Chalf != nullptr, epilogue also writes an fp16 copy.
__global__ void __launch_bounds__(256) k_gemm_mma(
    const __nv_bfloat16* __restrict__ A, const __nv_bfloat16* __restrict__ B,
    float* __restrict__ C, __half* __restrict__ Chalf, int M)
{
    extern __shared__ char sm[];
    uint32_t sbase = smem_u32(sm);
    const int tid = threadIdx.x;
    const int wid = tid >> 5, lid = tid & 31;
    const int bm = blockIdx.y * 128, bn = blockIdx.x * 128;
    const int wm = (wid >> 2) * 64, wn = (wid & 3) * 32;

    const int arow = (lid & 7) + ((lid >> 3) & 1) * 8;
    const int acol = (lid >> 4) * 8;
    const int q = lid >> 3;
    const int brow = (lid & 7) + (q >> 1) * 8;
    const int bcol = (q & 1) * 8;

    float acc[4][4][4];
#pragma unroll
    for (int mi = 0; mi < 4; mi++)
#pragma unroll
        for (int ni = 0; ni < 4; ni++)
#pragma unroll
            for (int j = 0; j < 4; j++) acc[mi][ni][j] = 0.f;

    auto load_chunk = [&](int c, int s) {
        uint32_t abase = sbase + s * 32768;
        int aoff = (c & 3) * 64 + ((c >= 8) ? 256 : 0);
#pragma unroll
        for (int it = 0; it < 4; it++) {
            int idx = tid + it * 256;
            int row = idx >> 3, col = (idx & 7) * 8;
            long ar = bm + row; if (ar >= M) ar = M - 1;
            cp16(abase + SWZ(row * 128 + col * 2), A + ar * KA + aoff + col);
        }
#pragma unroll
        for (int it = 0; it < 4; it++) {
            int idx = tid + it * 256;
            int row = idx >> 3, col = (idx & 7) * 8;
            cp16(abase + 16384 + SWZ(row * 128 + col * 2),
                 B + (long)(bn + row) * KK + c * 64 + col);
        }
        asm volatile("cp.async.commit_group;" ::: "memory");
    };

    auto compute_chunk = [&](int s) {
        uint32_t abase = sbase + s * 32768;
        uint32_t bbase = abase + 16384;
#pragma unroll
        for (int ks = 0; ks < 4; ks++) {
            uint32_t a[4][4];
#pragma unroll
            for (int mi = 0; mi < 4; mi++)
                ldm_x4(a[mi], abase + SWZ((wm + mi * 16 + arow) * 128 +
                                          (ks * 16 + acol) * 2));
            uint32_t b[2][4];
#pragma unroll
            for (int nj = 0; nj < 2; nj++)
                ldm_x4(b[nj], bbase + SWZ((wn + nj * 16 + brow) * 128 +
                                          (ks * 16 + bcol) * 2));
#pragma unroll
            for (int mi = 0; mi < 4; mi++)
#pragma unroll
                for (int ni = 0; ni < 4; ni++)
                    mma16816(acc[mi][ni], a[mi],
                             b[ni >> 1][(ni & 1) * 2], b[ni >> 1][(ni & 1) * 2 + 1]);
        }
    };

    load_chunk(0, 0);
    const int NC = 12;
    for (int c = 0; c < NC; c++) {
        if (c + 1 < NC) {
            load_chunk(c + 1, (c + 1) & 1);
            asm volatile("cp.async.wait_group 1;" ::: "memory");
        } else {
            asm volatile("cp.async.wait_group 0;" ::: "memory");
        }
        __syncthreads();
        compute_chunk(c & 1);
        __syncthreads();
    }

    const int g = lid >> 2, tig = lid & 3;
#pragma unroll
    for (int mi = 0; mi < 4; mi++) {
        int r0 = bm + wm + mi * 16 + g;
#pragma unroll
        for (int ni = 0; ni < 4; ni++) {
            int col = bn + wn + ni * 8 + tig * 2;
#pragma unroll
            for (int half2i = 0; half2i < 2; half2i++) {
                int r = r0 + half2i * 8;
                if (r < M) {
                    float c0 = acc[mi][ni][half2i * 2];
                    float c1 = acc[mi][ni][half2i * 2 + 1];
                    *(float2*)(C + (long)r * 256 + col) = make_float2(c0, c1);
                    if (Chalf)
                        *(__half2*)(Chalf + (long)r * 256 + col) =
                            __floats2half2_rn(c0, c1);
                }
            }
        }
    }
}

// ---------------- per-(node, head) attention projections --------------------
__global__ void k_scores(const float* __restrict__ attn) {
    int warp = (blockIdx.x * blockDim.x + threadIdx.x) >> 5;
    int lane = threadIdx.x & 31;
    if (warp >= NH) return;
    int n = warp >> 2, h = warp & 3;
    const float* hp = g_h + (long)n * HD + h * Dd;
    const float* ap = attn + h * 2 * Dd;
    float2 hv = *(const float2*)(hp + lane * 2);
    float2 as = *(const float2*)(ap + lane * 2);
    float2 ad = *(const float2*)(ap + Dd + lane * 2);
    float ssum = hv.x * as.x + hv.y * as.y;
    float dsum = hv.x * ad.x + hv.y * ad.y;
#pragma unroll
    for (int o = 16; o > 0; o >>= 1) {
        ssum += __shfl_xor_sync(0xFFFFFFFFu, ssum, o);
        dsum += __shfl_xor_sync(0xFFFFFFFFu, dsum, o);
    }
    if (lane == 0) { g_ssrc[warp] = ssum; g_sdst[warp] = dsum; }
}

__device__ __forceinline__ float leaky(float v) {
    return v > 0.f ? v : 0.2f * v;
}

// ---------------- edge pass: alpha = exp(leaky(e)), bucket into CSR ---------
__global__ void k_edge_sort(const int* __restrict__ ei) {
    int e = blockIdx.x * blockDim.x + threadIdx.x;
    if (e >= Ee) return;
    int s = ei[e], d = ei[Ee + e];
    float4 ss = *(const float4*)(g_ssrc + s * 4);
    float4 sd = *(const float4*)(g_sdst + d * 4);
    float4 al;
    al.x = __expf(leaky(ss.x + sd.x));
    al.y = __expf(leaky(ss.y + sd.y));
    al.z = __expf(leaky(ss.z + sd.z));
    al.w = __expf(leaky(ss.w + sd.w));
    int pos = atomicAdd(&g_cur[d], 1);
    g_srcs[pos] = s;
    *(float4*)(g_alp + (long)pos * 4) = al;
}

// ---------------- gather aggregation + normalize + split-bf16 pack ----------
// 64 threads per dst node; fp16 h gather; no atomics.
__global__ void __launch_bounds__(256) k_agg() {
    int d = blockIdx.x * 4 + (threadIdx.x >> 6);
    if (d >= Nn) return;
    int j = threadIdx.x & 63;        // 4-element group within 256-float row
    int h = j >> 4;
    int beg = g_off[d], cnt = g_cnt[d];
    float4 acc = make_float4(0.f, 0.f, 0.f, 0.f);
    float asum = 0.f;
    for (int k = beg; k < beg + cnt; k++) {
        int s = g_srcs[k];
        float a = g_alp[(long)k * 4 + h];
        const __half2* hp = (const __half2*)(g_hf + (long)s * HD + j * 4);
        float2 f0 = __half22float2(hp[0]);
        float2 f1 = __half22float2(hp[1]);
        asum += a;
        acc.x = fmaf(a, f0.x, acc.x);
        acc.y = fmaf(a, f0.y, acc.y);
        acc.z = fmaf(a, f1.x, acc.z);
        acc.w = fmaf(a, f1.y, acc.w);
    }
    float inv = 1.f / (asum + 1e-8f);
    float f[4] = { acc.x * inv, acc.y * inv, acc.z * inv, acc.w * inv };
    uint2 ph, pl;
    pack_split(f, ph, pl);
    long base = (long)d * KA + j * 4;
    *(uint2*)(g_o2 + base)       = ph;
    *(uint2*)(g_o2 + base + 256) = pl;
}

// ---------------- launch ----------------------------------------------------
extern "C" void kernel_launch(void* const* d_in, const int* in_sizes, int n_in,
                              void* d_out, int out_size)
{
    const float* x    = (const float*)d_in[0];
    const int*   ei   = (const int*)  d_in[1];
    const float* W    = (const float*)d_in[2];
    const float* attn = (const float*)d_in[3];
    const float* Wout = (const float*)d_in[4];
    float*       out  = (float*)d_out;

    void *p_h, *p_hf, *p_a2, *p_o2, *p_b1, *p_b2;
    cudaGetSymbolAddress(&p_h, g_h);
    cudaGetSymbolAddress(&p_hf, g_hf);
    cudaGetSymbolAddress(&p_a2, g_a2);
    cudaGetSymbolAddress(&p_o2, g_o2);
    cudaGetSymbolAddress(&p_b1, g_b1);
    cudaGetSymbolAddress(&p_b2, g_b2);

    cudaFuncSetAttribute(k_gemm_mma, cudaFuncAttributeMaxDynamicSharedMemorySize, 65536);

    int eb = (Ee + 255) / 256;

    k_init0<<<(Nn + 255) / 256, 256>>>();
    k_hist<<<eb, 256>>>(ei);
    k_scan<<<1, 1024>>>();
    k_prep_w<<<256, 256>>>(W, Wout);
    k_prep_x<<<(Nn * 64 + 255) / 256, 256>>>(x);

    dim3 gg(2, (Nn + 127) / 128);           // n-tiles fast -> A shared via L2
    k_gemm_mma<<<gg, 256, 65536>>>((const __nv_bfloat16*)p_a2,
                                   (const __nv_bfloat16*)p_b1,
                                   (float*)p_h, (__half*)p_hf, Nn);

    k_scores<<<(NH * 32 + 255) / 256, 256>>>(attn);

    k_edge_sort<<<eb, 256>>>(ei);

    k_agg<<<(Nn + 3) / 4, 256>>>();

    k_gemm_mma<<<gg, 256, 65536>>>((const __nv_bfloat16*)p_o2,
                                   (const __nv_bfloat16*)p_b2,
                                   out, (__half*)nullptr, Nn);
}

// round 8
// speedup vs baseline: 2.0826x; 1.0993x over previous
#include <cuda_runtime.h>
#include <cuda_bf16.h>
#include <cuda_fp16.h>
#include <math.h>
#include <stdint.h>

#define Nn   50000
#define Ee   1000000
#define Hh   4
#define Dd   64
#define NH   (Nn * Hh)   // 200000
#define HD   (Hh * Dd)   // 256
#define KA   512         // A storage: [Ah | Al]
#define KK   768         // B storage: [Bh | Bl | Bh]; virtual GEMM K

// ---------------- scratch (device globals; no allocation allowed) ----------
__device__ float  g_h[Nn * HD];     // per-node head features (fp32)
__device__ __half g_hf[Nn * HD];    // fp16 copy for the gather pass
__device__ float  g_ssrc[NH];
__device__ float  g_sdst[NH];
// CSR (dst-bucketed) edge structures
__device__ int    g_cnt[Nn];
__device__ int    g_off[Nn];
__device__ int    g_cur[Nn];
__device__ int    g_srcs[Ee];
__device__ float  g_alp[Ee * Hh];
// packed split-bf16 operands
__device__ __nv_bfloat16 g_a2[Nn * KA];    // [xh | xl]
__device__ __nv_bfloat16 g_o2[Nn * KA];    // normalized out_h packed [hi | lo]
__device__ __nv_bfloat16 g_b1[256 * KK];   // W  head-blocked, row n = out col
__device__ __nv_bfloat16 g_b2[256 * KK];   // W_out transposed

#define SWZ(o) ((o) ^ (((o) >> 3) & 0x70))

__device__ __forceinline__ uint32_t smem_u32(const void* p) {
    uint32_t a;
    asm("{ .reg .u64 t; cvta.to.shared.u64 t, %1; cvt.u32.u64 %0, t; }"
        : "=r"(a) : "l"(p));
    return a;
}
__device__ __forceinline__ void cp16(uint32_t dst, const void* src) {
    asm volatile("cp.async.cg.shared.global [%0], [%1], 16;"
                 :: "r"(dst), "l"(src) : "memory");
}
__device__ __forceinline__ void ldm_x4(uint32_t* r, uint32_t addr) {
    asm volatile("ldmatrix.sync.aligned.m8n8.x4.shared.b16 {%0,%1,%2,%3}, [%4];"
                 : "=r"(r[0]), "=r"(r[1]), "=r"(r[2]), "=r"(r[3]) : "r"(addr));
}
__device__ __forceinline__ void mma16816(float* c, const uint32_t* a,
                                         uint32_t b0, uint32_t b1) {
    asm volatile(
        "mma.sync.aligned.m16n8k16.row.col.f32.bf16.bf16.f32 "
        "{%0,%1,%2,%3}, {%4,%5,%6,%7}, {%8,%9}, {%0,%1,%2,%3};"
        : "+f"(c[0]), "+f"(c[1]), "+f"(c[2]), "+f"(c[3])
        : "r"(a[0]), "r"(a[1]), "r"(a[2]), "r"(a[3]), "r"(b0), "r"(b1));
}

// ---------------- init + CSR build ------------------------------------------
__global__ void k_init0() {
    int i = blockIdx.x * blockDim.x + threadIdx.x;
    if (i < Nn) g_cnt[i] = 0;
    if (i < NH) { g_ssrc[i] = 0.f; g_sdst[i] = 0.f; }
}
__global__ void k_hist(const int* __restrict__ ei) {
    int e = blockIdx.x * blockDim.x + threadIdx.x;
    if (e < Ee) atomicAdd(&g_cnt[ei[Ee + e]], 1);
}
__global__ void __launch_bounds__(1024) k_scan() {
    __shared__ int ts[1024];
    const int C = (Nn + 1023) / 1024;   // 49
    int tid = threadIdx.x;
    int beg = tid * C, end = min(beg + C, Nn);
    int sum = 0;
    for (int i = beg; i < end; i++) sum += g_cnt[i];
    ts[tid] = sum;
    __syncthreads();
    for (int o = 1; o < 1024; o <<= 1) {
        int v = (tid >= o) ? ts[tid - o] : 0;
        __syncthreads();
        ts[tid] += v;
        __syncthreads();
    }
    int run = (tid > 0) ? ts[tid - 1] : 0;
    for (int i = beg; i < end; i++) {
        int c = g_cnt[i];
        g_off[i] = run;
        g_cur[i] = run;
        run += c;
    }
}

// ---------------- weight prep: transpose + split-bf16 pack ------------------
__global__ void k_prep_w(const float* __restrict__ W, const float* __restrict__ Wout) {
    int t = blockIdx.x * 256 + threadIdx.x;   // 65536
    int n = t >> 8, k = t & 255;
    float v1 = W[(((n >> 6) * 256) + k) * 64 + (n & 63)];
    __nv_bfloat16 h1 = __float2bfloat16(v1);
    __nv_bfloat16 l1 = __float2bfloat16(v1 - __bfloat162float(h1));
    g_b1[n * KK + k]       = h1;
    g_b1[n * KK + 256 + k] = l1;
    g_b1[n * KK + 512 + k] = h1;
    float v2 = Wout[k * 256 + n];
    __nv_bfloat16 h2 = __float2bfloat16(v2);
    __nv_bfloat16 l2 = __float2bfloat16(v2 - __bfloat162float(h2));
    g_b2[n * KK + k]       = h2;
    g_b2[n * KK + 256 + k] = l2;
    g_b2[n * KK + 512 + k] = h2;
}

// ---------------- pack fp32 -> [hi | lo] bf16 -------------------------------
__device__ __forceinline__ void pack_split(const float* f, uint2& ph, uint2& pl) {
    unsigned short hs[4], ls[4];
#pragma unroll
    for (int i = 0; i < 4; i++) {
        __nv_bfloat16 h = __float2bfloat16(f[i]);
        __nv_bfloat16 l = __float2bfloat16(f[i] - __bfloat162float(h));
        hs[i] = __bfloat16_as_ushort(h);
        ls[i] = __bfloat16_as_ushort(l);
    }
    ph = make_uint2((uint32_t)hs[0] | ((uint32_t)hs[1] << 16),
                    (uint32_t)hs[2] | ((uint32_t)hs[3] << 16));
    pl = make_uint2((uint32_t)ls[0] | ((uint32_t)ls[1] << 16),
                    (uint32_t)ls[2] | ((uint32_t)ls[3] << 16));
}

__global__ void k_prep_x(const float* __restrict__ x) {
    int t = blockIdx.x * blockDim.x + threadIdx.x;   // per float4
    if (t >= Nn * 64) return;
    float4 v = ((const float4*)x)[t];
    float f[4] = { v.x, v.y, v.z, v.w };
    uint2 ph, pl;
    pack_split(f, ph, pl);
    long base = (long)(t >> 6) * KA + (t & 63) * 4;
    *(uint2*)(g_a2 + base)       = ph;
    *(uint2*)(g_a2 + base + 256) = pl;
}

// ---------------- bf16 mma.sync GEMM ----------------------------------------
// C[M,256] = A[M,512:(hi|lo)] x B[256,768:(Bh|Bl|Bh)]^T over virtual K=768.
// If attnp != nullptr, the epilogue also reduces attention scores
// (s_src/s_dst) via spread atomics — replaces the separate k_scores pass.
__global__ void __launch_bounds__(256) k_gemm_mma(
    const __nv_bfloat16* __restrict__ A, const __nv_bfloat16* __restrict__ B,
    float* __restrict__ C, __half* __restrict__ Chalf,
    const float* __restrict__ attnp, int M)
{
    extern __shared__ char sm[];
    uint32_t sbase = smem_u32(sm);
    const int tid = threadIdx.x;
    const int wid = tid >> 5, lid = tid & 31;
    const int bm = blockIdx.y * 128, bn = blockIdx.x * 128;
    const int wm = (wid >> 2) * 64, wn = (wid & 3) * 32;

    const int arow = (lid & 7) + ((lid >> 3) & 1) * 8;
    const int acol = (lid >> 4) * 8;
    const int q = lid >> 3;
    const int brow = (lid & 7) + (q >> 1) * 8;
    const int bcol = (q & 1) * 8;

    float acc[4][4][4];
#pragma unroll
    for (int mi = 0; mi < 4; mi++)
#pragma unroll
        for (int ni = 0; ni < 4; ni++)
#pragma unroll
            for (int j = 0; j < 4; j++) acc[mi][ni][j] = 0.f;

    auto load_chunk = [&](int c, int s) {
        uint32_t abase = sbase + s * 32768;
        int aoff = (c & 3) * 64 + ((c >= 8) ? 256 : 0);
#pragma unroll
        for (int it = 0; it < 4; it++) {
            int idx = tid + it * 256;
            int row = idx >> 3, col = (idx & 7) * 8;
            long ar = bm + row; if (ar >= M) ar = M - 1;
            cp16(abase + SWZ(row * 128 + col * 2), A + ar * KA + aoff + col);
        }
#pragma unroll
        for (int it = 0; it < 4; it++) {
            int idx = tid + it * 256;
            int row = idx >> 3, col = (idx & 7) * 8;
            cp16(abase + 16384 + SWZ(row * 128 + col * 2),
                 B + (long)(bn + row) * KK + c * 64 + col);
        }
        asm volatile("cp.async.commit_group;" ::: "memory");
    };

    auto compute_chunk = [&](int s) {
        uint32_t abase = sbase + s * 32768;
        uint32_t bbase = abase + 16384;
#pragma unroll
        for (int ks = 0; ks < 4; ks++) {
            uint32_t a[4][4];
#pragma unroll
            for (int mi = 0; mi < 4; mi++)
                ldm_x4(a[mi], abase + SWZ((wm + mi * 16 + arow) * 128 +
                                          (ks * 16 + acol) * 2));
            uint32_t b[2][4];
#pragma unroll
            for (int nj = 0; nj < 2; nj++)
                ldm_x4(b[nj], bbase + SWZ((wn + nj * 16 + brow) * 128 +
                                          (ks * 16 + bcol) * 2));
#pragma unroll
            for (int mi = 0; mi < 4; mi++)
#pragma unroll
                for (int ni = 0; ni < 4; ni++)
                    mma16816(acc[mi][ni], a[mi],
                             b[ni >> 1][(ni & 1) * 2], b[ni >> 1][(ni & 1) * 2 + 1]);
        }
    };

    load_chunk(0, 0);
    const int NC = 12;
    for (int c = 0; c < NC; c++) {
        if (c + 1 < NC) {
            load_chunk(c + 1, (c + 1) & 1);
            asm volatile("cp.async.wait_group 1;" ::: "memory");
        } else {
            asm volatile("cp.async.wait_group 0;" ::: "memory");
        }
        __syncthreads();
        compute_chunk(c & 1);
        __syncthreads();
    }

    const int g = lid >> 2, tig = lid & 3;

    // store C (+ optional fp16 copy)
#pragma unroll
    for (int mi = 0; mi < 4; mi++) {
        int r0 = bm + wm + mi * 16 + g;
#pragma unroll
        for (int ni = 0; ni < 4; ni++) {
            int col = bn + wn + ni * 8 + tig * 2;
#pragma unroll
            for (int h2 = 0; h2 < 2; h2++) {
                int r = r0 + h2 * 8;
                if (r < M) {
                    float c0 = acc[mi][ni][h2 * 2];
                    float c1 = acc[mi][ni][h2 * 2 + 1];
                    *(float2*)(C + (long)r * 256 + col) = make_float2(c0, c1);
                    if (Chalf)
                        *(__half2*)(Chalf + (long)r * 256 + col) =
                            __floats2half2_rn(c0, c1);
                }
            }
        }
    }

    // fused attention-score reduction (GEMM1 only)
    if (attnp) {
        int hh = ((bn + wn) >> 6) & 3;
        int dbase = (bn + wn) & 63;
        float as[8], ad[8];
#pragma unroll
        for (int ni = 0; ni < 4; ni++)
#pragma unroll
            for (int c2 = 0; c2 < 2; c2++) {
                int dd = dbase + ni * 8 + tig * 2 + c2;
                as[ni * 2 + c2] = __ldg(attnp + hh * 128 + dd);
                ad[ni * 2 + c2] = __ldg(attnp + hh * 128 + 64 + dd);
            }
#pragma unroll
        for (int mi = 0; mi < 4; mi++)
#pragma unroll
            for (int h2 = 0; h2 < 2; h2++) {
                int r = bm + wm + mi * 16 + g + h2 * 8;
                if (r < M) {
                    float ps = 0.f, pd = 0.f;
#pragma unroll
                    for (int ni = 0; ni < 4; ni++) {
                        float c0 = acc[mi][ni][h2 * 2];
                        float c1 = acc[mi][ni][h2 * 2 + 1];
                        ps += c0 * as[ni * 2] + c1 * as[ni * 2 + 1];
                        pd += c0 * ad[ni * 2] + c1 * ad[ni * 2 + 1];
                    }
                    atomicAdd(&g_ssrc[r * 4 + hh], ps);
                    atomicAdd(&g_sdst[r * 4 + hh], pd);
                }
            }
    }
}

__device__ __forceinline__ float leaky(float v) {
    return v > 0.f ? v : 0.2f * v;
}

// ---------------- edge pass: alpha = exp(leaky(e)), bucket into CSR ---------
__global__ void k_edge_sort(const int* __restrict__ ei) {
    int e = blockIdx.x * blockDim.x + threadIdx.x;
    if (e >= Ee) return;
    int s = ei[e], d = ei[Ee + e];
    float4 ss = *(const float4*)(g_ssrc + s * 4);
    float4 sd = *(const float4*)(g_sdst + d * 4);
    float4 al;
    al.x = __expf(leaky(ss.x + sd.x));
    al.y = __expf(leaky(ss.y + sd.y));
    al.z = __expf(leaky(ss.z + sd.z));
    al.w = __expf(leaky(ss.w + sd.w));
    int pos = atomicAdd(&g_cur[d], 1);
    g_srcs[pos] = s;
    *(float4*)(g_alp + (long)pos * 4) = al;
}

// ---------------- gather aggregation (smem-staged) + normalize + pack -------
// One 64-thread block per dst node. Edges staged 64-at-a-time into smem so
// the inner loop issues only independent g_hf gathers (high MLP, no
// redundant global src/alpha loads).
__global__ void __launch_bounds__(64) k_agg() {
    __shared__ int   s_src[64];
    __shared__ float s_alp[64][4];
    int d = blockIdx.x;
    int j = threadIdx.x;             // 0..63 : float4 group within 256-row
    int h = j >> 4;
    int beg = g_off[d], cnt = g_cnt[d];
    float4 acc = make_float4(0.f, 0.f, 0.f, 0.f);
    float asum = 0.f;
    for (int base = 0; base < cnt; base += 64) {
        int nb = min(64, cnt - base);
        if (j < nb) {
            int k = beg + base + j;
            s_src[j] = g_srcs[k];
            *(float4*)s_alp[j] = *(const float4*)(g_alp + (long)k * 4);
        }
        __syncthreads();
        for (int t = 0; t < nb; t++) {
            int s = s_src[t];
            float a = s_alp[t][h];
            const __half2* hp = (const __half2*)(g_hf + (long)s * HD + j * 4);
            float2 f0 = __half22float2(hp[0]);
            float2 f1 = __half22float2(hp[1]);
            asum += a;
            acc.x = fmaf(a, f0.x, acc.x);
            acc.y = fmaf(a, f0.y, acc.y);
            acc.z = fmaf(a, f1.x, acc.z);
            acc.w = fmaf(a, f1.y, acc.w);
        }
        __syncthreads();
    }
    float inv = 1.f / (asum + 1e-8f);
    float f[4] = { acc.x * inv, acc.y * inv, acc.z * inv, acc.w * inv };
    uint2 ph, pl;
    pack_split(f, ph, pl);
    long base2 = (long)d * KA + j * 4;
    *(uint2*)(g_o2 + base2)       = ph;
    *(uint2*)(g_o2 + base2 + 256) = pl;
}

// ---------------- launch ----------------------------------------------------
extern "C" void kernel_launch(void* const* d_in, const int* in_sizes, int n_in,
                              void* d_out, int out_size)
{
    const float* x    = (const float*)d_in[0];
    const int*   ei   = (const int*)  d_in[1];
    const float* W    = (const float*)d_in[2];
    const float* attn = (const float*)d_in[3];
    const float* Wout = (const float*)d_in[4];
    float*       out  = (float*)d_out;

    void *p_h, *p_hf, *p_a2, *p_o2, *p_b1, *p_b2;
    cudaGetSymbolAddress(&p_h, g_h);
    cudaGetSymbolAddress(&p_hf, g_hf);
    cudaGetSymbolAddress(&p_a2, g_a2);
    cudaGetSymbolAddress(&p_o2, g_o2);
    cudaGetSymbolAddress(&p_b1, g_b1);
    cudaGetSymbolAddress(&p_b2, g_b2);

    cudaFuncSetAttribute(k_gemm_mma, cudaFuncAttributeMaxDynamicSharedMemorySize, 65536);

    int eb = (Ee + 255) / 256;

    k_init0<<<(NH + 255) / 256, 256>>>();
    k_hist<<<eb, 256>>>(ei);
    k_scan<<<1, 1024>>>();
    k_prep_w<<<256, 256>>>(W, Wout);
    k_prep_x<<<(Nn * 64 + 255) / 256, 256>>>(x);

    dim3 gg(2, (Nn + 127) / 128);           // n-tiles fast -> A shared via L2
    k_gemm_mma<<<gg, 256, 65536>>>((const __nv_bfloat16*)p_a2,
                                   (const __nv_bfloat16*)p_b1,
                                   (float*)p_h, (__half*)p_hf, attn, Nn);

    k_edge_sort<<<eb, 256>>>(ei);

    k_agg<<<Nn, 64>>>();

    k_gemm_mma<<<gg, 256, 65536>>>((const __nv_bfloat16*)p_o2,
                                   (const __nv_bfloat16*)p_b2,
                                   out, (__half*)nullptr, (const float*)nullptr, Nn);
}

// round 9
// speedup vs baseline: 2.1107x; 1.0135x over previous
#include <cuda_runtime.h>
#include <cuda_bf16.h>
#include <cuda_fp16.h>
#include <math.h>
#include <stdint.h>

#define Nn   50000
#define Ee   1000000
#define Hh   4
#define Dd   64
#define NH   (Nn * Hh)   // 200000
#define HD   (Hh * Dd)   // 256
#define KA   512         // A storage: [Ah | Al]
#define KK   768         // B storage: [Bh | Bl | Bh]; virtual GEMM K

// ---------------- scratch (device globals; no allocation allowed) ----------
__device__ __half g_hf[Nn * HD];    // fp16 node features for the gather pass
__device__ float  g_ssrc[NH];
__device__ float  g_sdst[NH];
// CSR (dst-bucketed) edge structures
__device__ int    g_cnt[Nn];
__device__ int    g_off[Nn];
__device__ int    g_cur[Nn];
__device__ int    g_srcs[Ee];
__device__ __half g_alp[Ee * Hh];   // fp16 alpha (4 per sorted edge slot)
// packed split-bf16 operands
__device__ __nv_bfloat16 g_a2[Nn * KA];    // [xh | xl]
__device__ __nv_bfloat16 g_o2[Nn * KA];    // normalized out_h packed [hi | lo]
__device__ __nv_bfloat16 g_b1[256 * KK];   // W  head-blocked, row n = out col
__device__ __nv_bfloat16 g_b2[256 * KK];   // W_out transposed

#define SWZ(o) ((o) ^ (((o) >> 3) & 0x70))

__device__ __forceinline__ uint32_t smem_u32(const void* p) {
    uint32_t a;
    asm("{ .reg .u64 t; cvta.to.shared.u64 t, %1; cvt.u32.u64 %0, t; }"
        : "=r"(a) : "l"(p));
    return a;
}
__device__ __forceinline__ void cp16(uint32_t dst, const void* src) {
    asm volatile("cp.async.cg.shared.global [%0], [%1], 16;"
                 :: "r"(dst), "l"(src) : "memory");
}
__device__ __forceinline__ void ldm_x4(uint32_t* r, uint32_t addr) {
    asm volatile("ldmatrix.sync.aligned.m8n8.x4.shared.b16 {%0,%1,%2,%3}, [%4];"
                 : "=r"(r[0]), "=r"(r[1]), "=r"(r[2]), "=r"(r[3]) : "r"(addr));
}
__device__ __forceinline__ void mma16816(float* c, const uint32_t* a,
                                         uint32_t b0, uint32_t b1) {
    asm volatile(
        "mma.sync.aligned.m16n8k16.row.col.f32.bf16.bf16.f32 "
        "{%0,%1,%2,%3}, {%4,%5,%6,%7}, {%8,%9}, {%0,%1,%2,%3};"
        : "+f"(c[0]), "+f"(c[1]), "+f"(c[2]), "+f"(c[3])
        : "r"(a[0]), "r"(a[1]), "r"(a[2]), "r"(a[3]), "r"(b0), "r"(b1));
}

// ---------------- init + CSR build ------------------------------------------
__global__ void k_init0() {
    int i = blockIdx.x * blockDim.x + threadIdx.x;
    if (i < Nn) g_cnt[i] = 0;
    if (i < NH) { g_ssrc[i] = 0.f; g_sdst[i] = 0.f; }
}
__global__ void k_hist(const int* __restrict__ ei) {
    int e = blockIdx.x * blockDim.x + threadIdx.x;
    if (e < Ee) atomicAdd(&g_cnt[ei[Ee + e]], 1);
}
__global__ void __launch_bounds__(1024) k_scan() {
    __shared__ int ts[1024];
    const int C = (Nn + 1023) / 1024;   // 49
    int tid = threadIdx.x;
    int beg = tid * C, end = min(beg + C, Nn);
    int sum = 0;
    for (int i = beg; i < end; i++) sum += g_cnt[i];
    ts[tid] = sum;
    __syncthreads();
    for (int o = 1; o < 1024; o <<= 1) {
        int v = (tid >= o) ? ts[tid - o] : 0;
        __syncthreads();
        ts[tid] += v;
        __syncthreads();
    }
    int run = (tid > 0) ? ts[tid - 1] : 0;
    for (int i = beg; i < end; i++) {
        int c = g_cnt[i];
        g_off[i] = run;
        g_cur[i] = run;
        run += c;
    }
}

// ---------------- weight prep: transpose + split-bf16 pack ------------------
__global__ void k_prep_w(const float* __restrict__ W, const float* __restrict__ Wout) {
    int t = blockIdx.x * 256 + threadIdx.x;   // 65536
    int n = t >> 8, k = t & 255;
    float v1 = W[(((n >> 6) * 256) + k) * 64 + (n & 63)];
    __nv_bfloat16 h1 = __float2bfloat16(v1);
    __nv_bfloat16 l1 = __float2bfloat16(v1 - __bfloat162float(h1));
    g_b1[n * KK + k]       = h1;
    g_b1[n * KK + 256 + k] = l1;
    g_b1[n * KK + 512 + k] = h1;
    float v2 = Wout[k * 256 + n];
    __nv_bfloat16 h2 = __float2bfloat16(v2);
    __nv_bfloat16 l2 = __float2bfloat16(v2 - __bfloat162float(h2));
    g_b2[n * KK + k]       = h2;
    g_b2[n * KK + 256 + k] = l2;
    g_b2[n * KK + 512 + k] = h2;
}

// ---------------- pack fp32 -> [hi | lo] bf16 -------------------------------
__device__ __forceinline__ void pack_split(const float* f, uint2& ph, uint2& pl) {
    unsigned short hs[4], ls[4];
#pragma unroll
    for (int i = 0; i < 4; i++) {
        __nv_bfloat16 h = __float2bfloat16(f[i]);
        __nv_bfloat16 l = __float2bfloat16(f[i] - __bfloat162float(h));
        hs[i] = __bfloat16_as_ushort(h);
        ls[i] = __bfloat16_as_ushort(l);
    }
    ph = make_uint2((uint32_t)hs[0] | ((uint32_t)hs[1] << 16),
                    (uint32_t)hs[2] | ((uint32_t)hs[3] << 16));
    pl = make_uint2((uint32_t)ls[0] | ((uint32_t)ls[1] << 16),
                    (uint32_t)ls[2] | ((uint32_t)ls[3] << 16));
}

__global__ void k_prep_x(const float* __restrict__ x) {
    int t = blockIdx.x * blockDim.x + threadIdx.x;   // per float4
    if (t >= Nn * 64) return;
    float4 v = ((const float4*)x)[t];
    float f[4] = { v.x, v.y, v.z, v.w };
    uint2 ph, pl;
    pack_split(f, ph, pl);
    long base = (long)(t >> 6) * KA + (t & 63) * 4;
    *(uint2*)(g_a2 + base)       = ph;
    *(uint2*)(g_a2 + base + 256) = pl;
}

// ---------------- bf16 mma.sync GEMM ----------------------------------------
// C[M,256] = A[M,512:(hi|lo)] x B[256,768:(Bh|Bl|Bh)]^T over virtual K=768.
// C may be nullptr (fp32 result not needed); Chalf optional fp16 copy;
// attnp != nullptr fuses the attention-score reduction into the epilogue.
__global__ void __launch_bounds__(256) k_gemm_mma(
    const __nv_bfloat16* __restrict__ A, const __nv_bfloat16* __restrict__ B,
    float* __restrict__ C, __half* __restrict__ Chalf,
    const float* __restrict__ attnp, int M)
{
    extern __shared__ char sm[];
    uint32_t sbase = smem_u32(sm);
    const int tid = threadIdx.x;
    const int wid = tid >> 5, lid = tid & 31;
    const int bm = blockIdx.y * 128, bn = blockIdx.x * 128;
    const int wm = (wid >> 2) * 64, wn = (wid & 3) * 32;

    const int arow = (lid & 7) + ((lid >> 3) & 1) * 8;
    const int acol = (lid >> 4) * 8;
    const int q = lid >> 3;
    const int brow = (lid & 7) + (q >> 1) * 8;
    const int bcol = (q & 1) * 8;

    float acc[4][4][4];
#pragma unroll
    for (int mi = 0; mi < 4; mi++)
#pragma unroll
        for (int ni = 0; ni < 4; ni++)
#pragma unroll
            for (int j = 0; j < 4; j++) acc[mi][ni][j] = 0.f;

    auto load_chunk = [&](int c, int s) {
        uint32_t abase = sbase + s * 32768;
        int aoff = (c & 3) * 64 + ((c >= 8) ? 256 : 0);
#pragma unroll
        for (int it = 0; it < 4; it++) {
            int idx = tid + it * 256;
            int row = idx >> 3, col = (idx & 7) * 8;
            long ar = bm + row; if (ar >= M) ar = M - 1;
            cp16(abase + SWZ(row * 128 + col * 2), A + ar * KA + aoff + col);
        }
#pragma unroll
        for (int it = 0; it < 4; it++) {
            int idx = tid + it * 256;
            int row = idx >> 3, col = (idx & 7) * 8;
            cp16(abase + 16384 + SWZ(row * 128 + col * 2),
                 B + (long)(bn + row) * KK + c * 64 + col);
        }
        asm volatile("cp.async.commit_group;" ::: "memory");
    };

    auto compute_chunk = [&](int s) {
        uint32_t abase = sbase + s * 32768;
        uint32_t bbase = abase + 16384;
#pragma unroll
        for (int ks = 0; ks < 4; ks++) {
            uint32_t a[4][4];
#pragma unroll
            for (int mi = 0; mi < 4; mi++)
                ldm_x4(a[mi], abase + SWZ((wm + mi * 16 + arow) * 128 +
                                          (ks * 16 + acol) * 2));
            uint32_t b[2][4];
#pragma unroll
            for (int nj = 0; nj < 2; nj++)
                ldm_x4(b[nj], bbase + SWZ((wn + nj * 16 + brow) * 128 +
                                          (ks * 16 + bcol) * 2));
#pragma unroll
            for (int mi = 0; mi < 4; mi++)
#pragma unroll
                for (int ni = 0; ni < 4; ni++)
                    mma16816(acc[mi][ni], a[mi],
                             b[ni >> 1][(ni & 1) * 2], b[ni >> 1][(ni & 1) * 2 + 1]);
        }
    };

    load_chunk(0, 0);
    const int NC = 12;
    for (int c = 0; c < NC; c++) {
        if (c + 1 < NC) {
            load_chunk(c + 1, (c + 1) & 1);
            asm volatile("cp.async.wait_group 1;" ::: "memory");
        } else {
            asm volatile("cp.async.wait_group 0;" ::: "memory");
        }
        __syncthreads();
        compute_chunk(c & 1);
        __syncthreads();
    }

    const int g = lid >> 2, tig = lid & 3;

    // store C (fp32 optional) / fp16 copy (optional)
#pragma unroll
    for (int mi = 0; mi < 4; mi++) {
        int r0 = bm + wm + mi * 16 + g;
#pragma unroll
        for (int ni = 0; ni < 4; ni++) {
            int col = bn + wn + ni * 8 + tig * 2;
#pragma unroll
            for (int h2 = 0; h2 < 2; h2++) {
                int r = r0 + h2 * 8;
                if (r < M) {
                    float c0 = acc[mi][ni][h2 * 2];
                    float c1 = acc[mi][ni][h2 * 2 + 1];
                    if (C)
                        *(float2*)(C + (long)r * 256 + col) = make_float2(c0, c1);
                    if (Chalf)
                        *(__half2*)(Chalf + (long)r * 256 + col) =
                            __floats2half2_rn(c0, c1);
                }
            }
        }
    }

    // fused attention-score reduction (GEMM1 only)
    if (attnp) {
        int hh = ((bn + wn) >> 6) & 3;
        int dbase = (bn + wn) & 63;
        float as[8], ad[8];
#pragma unroll
        for (int ni = 0; ni < 4; ni++)
#pragma unroll
            for (int c2 = 0; c2 < 2; c2++) {
                int dd = dbase + ni * 8 + tig * 2 + c2;
                as[ni * 2 + c2] = __ldg(attnp + hh * 128 + dd);
                ad[ni * 2 + c2] = __ldg(attnp + hh * 128 + 64 + dd);
            }
#pragma unroll
        for (int mi = 0; mi < 4; mi++)
#pragma unroll
            for (int h2 = 0; h2 < 2; h2++) {
                int r = bm + wm + mi * 16 + g + h2 * 8;
                if (r < M) {
                    float ps = 0.f, pd = 0.f;
#pragma unroll
                    for (int ni = 0; ni < 4; ni++) {
                        float c0 = acc[mi][ni][h2 * 2];
                        float c1 = acc[mi][ni][h2 * 2 + 1];
                        ps += c0 * as[ni * 2] + c1 * as[ni * 2 + 1];
                        pd += c0 * ad[ni * 2] + c1 * ad[ni * 2 + 1];
                    }
                    atomicAdd(&g_ssrc[r * 4 + hh], ps);
                    atomicAdd(&g_sdst[r * 4 + hh], pd);
                }
            }
    }
}

__device__ __forceinline__ float leaky(float v) {
    return v > 0.f ? v : 0.2f * v;
}

// ---------------- edge pass: alpha = exp(leaky(e)), bucket into CSR ---------
// 4 edges per thread (int4 loads) to batch the dependent load chains.
__global__ void k_edge_sort(const int* __restrict__ ei) {
    int t = blockIdx.x * blockDim.x + threadIdx.x;
    int e0 = t * 4;
    if (e0 >= Ee) return;
    int4 sv = *(const int4*)(ei + e0);
    int4 dv = *(const int4*)(ei + Ee + e0);
    int ss4[4] = { sv.x, sv.y, sv.z, sv.w };
    int dd4[4] = { dv.x, dv.y, dv.z, dv.w };
    float4 ssr[4], sdr[4];
#pragma unroll
    for (int i = 0; i < 4; i++) {
        ssr[i] = *(const float4*)(g_ssrc + ss4[i] * 4);
        sdr[i] = *(const float4*)(g_sdst + dd4[i] * 4);
    }
#pragma unroll
    for (int i = 0; i < 4; i++) {
        float a0 = __expf(leaky(ssr[i].x + sdr[i].x));
        float a1 = __expf(leaky(ssr[i].y + sdr[i].y));
        float a2 = __expf(leaky(ssr[i].z + sdr[i].z));
        float a3 = __expf(leaky(ssr[i].w + sdr[i].w));
        __half2 p01 = __floats2half2_rn(a0, a1);
        __half2 p23 = __floats2half2_rn(a2, a3);
        int pos = atomicAdd(&g_cur[dd4[i]], 1);
        g_srcs[pos] = ss4[i];
        uint2 pk;
        pk.x = *(uint32_t*)&p01;
        pk.y = *(uint32_t*)&p23;
        *(uint2*)(g_alp + (long)pos * 4) = pk;
    }
}

// ---------------- gather aggregation (smem-staged) + normalize + pack -------
__global__ void __launch_bounds__(64) k_agg() {
    __shared__ int  s_src[64];
    __shared__ uint2 s_alp[64];      // half4 per staged edge
    int d = blockIdx.x;
    int j = threadIdx.x;             // 0..63 : float4 group within 256-row
    int h = j >> 4;
    int beg = g_off[d], cnt = g_cnt[d];
    float4 acc = make_float4(0.f, 0.f, 0.f, 0.f);
    float asum = 0.f;
    for (int base = 0; base < cnt; base += 64) {
        int nb = min(64, cnt - base);
        if (j < nb) {
            int k = beg + base + j;
            s_src[j] = g_srcs[k];
            s_alp[j] = *(const uint2*)(g_alp + (long)k * 4);
        }
        __syncthreads();
#pragma unroll 4
        for (int t = 0; t < nb; t++) {
            int s = s_src[t];
            uint2 pa = s_alp[t];
            uint32_t w = (h & 2) ? pa.y : pa.x;
            __half2 hp2 = *(__half2*)&w;
            float a = (h & 1) ? __high2float(hp2) : __low2float(hp2);
            const __half2* hp = (const __half2*)(g_hf + (long)s * HD + j * 4);
            float2 f0 = __half22float2(hp[0]);
            float2 f1 = __half22float2(hp[1]);
            asum += a;
            acc.x = fmaf(a, f0.x, acc.x);
            acc.y = fmaf(a, f0.y, acc.y);
            acc.z = fmaf(a, f1.x, acc.z);
            acc.w = fmaf(a, f1.y, acc.w);
        }
        __syncthreads();
    }
    float inv = 1.f / (asum + 1e-8f);
    float f[4] = { acc.x * inv, acc.y * inv, acc.z * inv, acc.w * inv };
    uint2 ph, pl;
    pack_split(f, ph, pl);
    long base2 = (long)d * KA + j * 4;
    *(uint2*)(g_o2 + base2)       = ph;
    *(uint2*)(g_o2 + base2 + 256) = pl;
}

// ---------------- launch ----------------------------------------------------
extern "C" void kernel_launch(void* const* d_in, const int* in_sizes, int n_in,
                              void* d_out, int out_size)
{
    const float* x    = (const float*)d_in[0];
    const int*   ei   = (const int*)  d_in[1];
    const float* W    = (const float*)d_in[2];
    const float* attn = (const float*)d_in[3];
    const float* Wout = (const float*)d_in[4];
    float*       out  = (float*)d_out;

    void *p_hf, *p_a2, *p_o2, *p_b1, *p_b2;
    cudaGetSymbolAddress(&p_hf, g_hf);
    cudaGetSymbolAddress(&p_a2, g_a2);
    cudaGetSymbolAddress(&p_o2, g_o2);
    cudaGetSymbolAddress(&p_b1, g_b1);
    cudaGetSymbolAddress(&p_b2, g_b2);

    cudaFuncSetAttribute(k_gemm_mma, cudaFuncAttributeMaxDynamicSharedMemorySize, 65536);

    int eb = (Ee + 255) / 256;

    k_init0<<<(NH + 255) / 256, 256>>>();
    k_hist<<<eb, 256>>>(ei);
    k_scan<<<1, 1024>>>();
    k_prep_w<<<256, 256>>>(W, Wout);
    k_prep_x<<<(Nn * 64 + 255) / 256, 256>>>(x);

    dim3 gg(2, (Nn + 127) / 128);           // n-tiles fast -> A shared via L2
    k_gemm_mma<<<gg, 256, 65536>>>((const __nv_bfloat16*)p_a2,
                                   (const __nv_bfloat16*)p_b1,
                                   (float*)nullptr, (__half*)p_hf, attn, Nn);

    k_edge_sort<<<(Ee / 4 + 255) / 256, 256>>>(ei);

    k_agg<<<Nn, 64>>>();

    k_gemm_mma<<<gg, 256, 65536>>>((const __nv_bfloat16*)p_o2,
                                   (const __nv_bfloat16*)p_b2,
                                   out, (__half*)nullptr, (const float*)nullptr, Nn);
}

// round 10
// speedup vs baseline: 2.7092x; 1.2836x over previous
#include <cuda_runtime.h>
#include <cuda_bf16.h>
#include <cuda_fp16.h>
#include <math.h>
#include <stdint.h>

#define Nn   50000
#define Ee   1000000
#define Hh   4
#define Dd   64
#define NH   (Nn * Hh)   // 200000
#define HD   (Hh * Dd)   // 256
#define KA   512         // A storage: [Ah | Al]
#define KK   768         // B storage: [Bh | Bl | Bh]; virtual GEMM K

// ---------------- scratch (device globals; no allocation allowed) ----------
__device__ __half g_hf[Nn * HD];    // fp16 node features for the gather pass
__device__ float  g_ssrc[NH];
__device__ float  g_sdst[NH];
// CSR (dst-bucketed) edge structures
__device__ int    g_cnt[Nn];
__device__ int    g_off[Nn];
__device__ int    g_cur[Nn];
__device__ int    g_srcs[Ee];
__device__ int    g_total;          // global offset counter
// packed split-bf16 operands
__device__ __nv_bfloat16 g_a2[Nn * KA];    // [xh | xl]
__device__ __nv_bfloat16 g_o2[Nn * KA];    // normalized out_h packed [hi | lo]
__device__ __nv_bfloat16 g_b1[256 * KK];   // W  head-blocked, row n = out col
__device__ __nv_bfloat16 g_b2[256 * KK];   // W_out transposed

#define SWZ(o) ((o) ^ (((o) >> 3) & 0x70))

__device__ __forceinline__ uint32_t smem_u32(const void* p) {
    uint32_t a;
    asm("{ .reg .u64 t; cvta.to.shared.u64 t, %1; cvt.u32.u64 %0, t; }"
        : "=r"(a) : "l"(p));
    return a;
}
__device__ __forceinline__ void cp16(uint32_t dst, const void* src) {
    asm volatile("cp.async.cg.shared.global [%0], [%1], 16;"
                 :: "r"(dst), "l"(src) : "memory");
}
__device__ __forceinline__ void ldm_x4(uint32_t* r, uint32_t addr) {
    asm volatile("ldmatrix.sync.aligned.m8n8.x4.shared.b16 {%0,%1,%2,%3}, [%4];"
                 : "=r"(r[0]), "=r"(r[1]), "=r"(r[2]), "=r"(r[3]) : "r"(addr));
}
__device__ __forceinline__ void mma16816(float* c, const uint32_t* a,
                                         uint32_t b0, uint32_t b1) {
    asm volatile(
        "mma.sync.aligned.m16n8k16.row.col.f32.bf16.bf16.f32 "
        "{%0,%1,%2,%3}, {%4,%5,%6,%7}, {%8,%9}, {%0,%1,%2,%3};"
        : "+f"(c[0]), "+f"(c[1]), "+f"(c[2]), "+f"(c[3])
        : "r"(a[0]), "r"(a[1]), "r"(a[2]), "r"(a[3]), "r"(b0), "r"(b1));
}

// ---------------- init + CSR build ------------------------------------------
__global__ void k_init0() {
    int i = blockIdx.x * blockDim.x + threadIdx.x;
    if (i == 0) g_total = 0;
    if (i < Nn) g_cnt[i] = 0;
    if (i < NH) { g_ssrc[i] = 0.f; g_sdst[i] = 0.f; }
}
__global__ void k_hist(const int* __restrict__ ei) {
    int e = blockIdx.x * blockDim.x + threadIdx.x;
    if (e < Ee) atomicAdd(&g_cnt[ei[Ee + e]], 1);
}
// parallel offsets: warp-scan + one global atomic per warp. Offsets are
// disjoint ranges (order across warps is arbitrary — CSR doesn't care).
__global__ void k_offs() {
    int i = blockIdx.x * blockDim.x + threadIdx.x;
    int lane = threadIdx.x & 31;
    int c = (i < Nn) ? g_cnt[i] : 0;
    int incl = c;
#pragma unroll
    for (int o = 1; o < 32; o <<= 1) {
        int v = __shfl_up_sync(0xFFFFFFFFu, incl, o);
        if (lane >= o) incl += v;
    }
    int total = __shfl_sync(0xFFFFFFFFu, incl, 31);
    int base = 0;
    if (lane == 31) base = atomicAdd(&g_total, total);
    base = __shfl_sync(0xFFFFFFFFu, base, 31);
    int off = base + incl - c;
    if (i < Nn) { g_off[i] = off; g_cur[i] = off; }
}

// ---------------- weight prep: transpose + split-bf16 pack ------------------
__global__ void k_prep_w(const float* __restrict__ W, const float* __restrict__ Wout) {
    int t = blockIdx.x * 256 + threadIdx.x;   // 65536
    int n = t >> 8, k = t & 255;
    float v1 = W[(((n >> 6) * 256) + k) * 64 + (n & 63)];
    __nv_bfloat16 h1 = __float2bfloat16(v1);
    __nv_bfloat16 l1 = __float2bfloat16(v1 - __bfloat162float(h1));
    g_b1[n * KK + k]       = h1;
    g_b1[n * KK + 256 + k] = l1;
    g_b1[n * KK + 512 + k] = h1;
    float v2 = Wout[k * 256 + n];
    __nv_bfloat16 h2 = __float2bfloat16(v2);
    __nv_bfloat16 l2 = __float2bfloat16(v2 - __bfloat162float(h2));
    g_b2[n * KK + k]       = h2;
    g_b2[n * KK + 256 + k] = l2;
    g_b2[n * KK + 512 + k] = h2;
}

// ---------------- pack fp32 -> [hi | lo] bf16 -------------------------------
__device__ __forceinline__ void pack_split(const float* f, uint2& ph, uint2& pl) {
    unsigned short hs[4], ls[4];
#pragma unroll
    for (int i = 0; i < 4; i++) {
        __nv_bfloat16 h = __float2bfloat16(f[i]);
        __nv_bfloat16 l = __float2bfloat16(f[i] - __bfloat162float(h));
        hs[i] = __bfloat16_as_ushort(h);
        ls[i] = __bfloat16_as_ushort(l);
    }
    ph = make_uint2((uint32_t)hs[0] | ((uint32_t)hs[1] << 16),
                    (uint32_t)hs[2] | ((uint32_t)hs[3] << 16));
    pl = make_uint2((uint32_t)ls[0] | ((uint32_t)ls[1] << 16),
                    (uint32_t)ls[2] | ((uint32_t)ls[3] << 16));
}

__global__ void k_prep_x(const float* __restrict__ x) {
    int t = blockIdx.x * blockDim.x + threadIdx.x;   // per float4
    if (t >= Nn * 64) return;
    float4 v = ((const float4*)x)[t];
    float f[4] = { v.x, v.y, v.z, v.w };
    uint2 ph, pl;
    pack_split(f, ph, pl);
    long base = (long)(t >> 6) * KA + (t & 63) * 4;
    *(uint2*)(g_a2 + base)       = ph;
    *(uint2*)(g_a2 + base + 256) = pl;
}

// ---------------- bf16 mma.sync GEMM ----------------------------------------
// C[M,256] = A[M,512:(hi|lo)] x B[256,768:(Bh|Bl|Bh)]^T over virtual K=768.
// C may be nullptr; Chalf optional fp16 copy; attnp != nullptr fuses the
// attention-score reduction into the epilogue.
__global__ void __launch_bounds__(256) k_gemm_mma(
    const __nv_bfloat16* __restrict__ A, const __nv_bfloat16* __restrict__ B,
    float* __restrict__ C, __half* __restrict__ Chalf,
    const float* __restrict__ attnp, int M)
{
    extern __shared__ char sm[];
    uint32_t sbase = smem_u32(sm);
    const int tid = threadIdx.x;
    const int wid = tid >> 5, lid = tid & 31;
    const int bm = blockIdx.y * 128, bn = blockIdx.x * 128;
    const int wm = (wid >> 2) * 64, wn = (wid & 3) * 32;

    const int arow = (lid & 7) + ((lid >> 3) & 1) * 8;
    const int acol = (lid >> 4) * 8;
    const int q = lid >> 3;
    const int brow = (lid & 7) + (q >> 1) * 8;
    const int bcol = (q & 1) * 8;

    float acc[4][4][4];
#pragma unroll
    for (int mi = 0; mi < 4; mi++)
#pragma unroll
        for (int ni = 0; ni < 4; ni++)
#pragma unroll
            for (int j = 0; j < 4; j++) acc[mi][ni][j] = 0.f;

    auto load_chunk = [&](int c, int s) {
        uint32_t abase = sbase + s * 32768;
        int aoff = (c & 3) * 64 + ((c >= 8) ? 256 : 0);
#pragma unroll
        for (int it = 0; it < 4; it++) {
            int idx = tid + it * 256;
            int row = idx >> 3, col = (idx & 7) * 8;
            long ar = bm + row; if (ar >= M) ar = M - 1;
            cp16(abase + SWZ(row * 128 + col * 2), A + ar * KA + aoff + col);
        }
#pragma unroll
        for (int it = 0; it < 4; it++) {
            int idx = tid + it * 256;
            int row = idx >> 3, col = (idx & 7) * 8;
            cp16(abase + 16384 + SWZ(row * 128 + col * 2),
                 B + (long)(bn + row) * KK + c * 64 + col);
        }
        asm volatile("cp.async.commit_group;" ::: "memory");
    };

    auto compute_chunk = [&](int s) {
        uint32_t abase = sbase + s * 32768;
        uint32_t bbase = abase + 16384;
#pragma unroll
        for (int ks = 0; ks < 4; ks++) {
            uint32_t a[4][4];
#pragma unroll
            for (int mi = 0; mi < 4; mi++)
                ldm_x4(a[mi], abase + SWZ((wm + mi * 16 + arow) * 128 +
                                          (ks * 16 + acol) * 2));
            uint32_t b[2][4];
#pragma unroll
            for (int nj = 0; nj < 2; nj++)
                ldm_x4(b[nj], bbase + SWZ((wn + nj * 16 + brow) * 128 +
                                          (ks * 16 + bcol) * 2));
#pragma unroll
            for (int mi = 0; mi < 4; mi++)
#pragma unroll
                for (int ni = 0; ni < 4; ni++)
                    mma16816(acc[mi][ni], a[mi],
                             b[ni >> 1][(ni & 1) * 2], b[ni >> 1][(ni & 1) * 2 + 1]);
        }
    };

    load_chunk(0, 0);
    const int NC = 12;
    for (int c = 0; c < NC; c++) {
        if (c + 1 < NC) {
            load_chunk(c + 1, (c + 1) & 1);
            asm volatile("cp.async.wait_group 1;" ::: "memory");
        } else {
            asm volatile("cp.async.wait_group 0;" ::: "memory");
        }
        __syncthreads();
        compute_chunk(c & 1);
        __syncthreads();
    }

    const int g = lid >> 2, tig = lid & 3;

#pragma unroll
    for (int mi = 0; mi < 4; mi++) {
        int r0 = bm + wm + mi * 16 + g;
#pragma unroll
        for (int ni = 0; ni < 4; ni++) {
            int col = bn + wn + ni * 8 + tig * 2;
#pragma unroll
            for (int h2 = 0; h2 < 2; h2++) {
                int r = r0 + h2 * 8;
                if (r < M) {
                    float c0 = acc[mi][ni][h2 * 2];
                    float c1 = acc[mi][ni][h2 * 2 + 1];
                    if (C)
                        *(float2*)(C + (long)r * 256 + col) = make_float2(c0, c1);
                    if (Chalf)
                        *(__half2*)(Chalf + (long)r * 256 + col) =
                            __floats2half2_rn(c0, c1);
                }
            }
        }
    }

    // fused attention-score reduction (GEMM1 only)
    if (attnp) {
        int hh = ((bn + wn) >> 6) & 3;
        int dbase = (bn + wn) & 63;
        float as[8], ad[8];
#pragma unroll
        for (int ni = 0; ni < 4; ni++)
#pragma unroll
            for (int c2 = 0; c2 < 2; c2++) {
                int dd = dbase + ni * 8 + tig * 2 + c2;
                as[ni * 2 + c2] = __ldg(attnp + hh * 128 + dd);
                ad[ni * 2 + c2] = __ldg(attnp + hh * 128 + 64 + dd);
            }
#pragma unroll
        for (int mi = 0; mi < 4; mi++)
#pragma unroll
            for (int h2 = 0; h2 < 2; h2++) {
                int r = bm + wm + mi * 16 + g + h2 * 8;
                if (r < M) {
                    float ps = 0.f, pd = 0.f;
#pragma unroll
                    for (int ni = 0; ni < 4; ni++) {
                        float c0 = acc[mi][ni][h2 * 2];
                        float c1 = acc[mi][ni][h2 * 2 + 1];
                        ps += c0 * as[ni * 2] + c1 * as[ni * 2 + 1];
                        pd += c0 * ad[ni * 2] + c1 * ad[ni * 2 + 1];
                    }
                    atomicAdd(&g_ssrc[r * 4 + hh], ps);
                    atomicAdd(&g_sdst[r * 4 + hh], pd);
                }
            }
    }
}

__device__ __forceinline__ float leaky(float v) {
    return v > 0.f ? v : 0.2f * v;
}

// ---------------- edge pass: pure permutation build (no scores needed) ------
__global__ void k_edge_sort(const int* __restrict__ ei) {
    int t = blockIdx.x * blockDim.x + threadIdx.x;
    int e0 = t * 4;
    if (e0 >= Ee) return;
    int4 sv = *(const int4*)(ei + e0);
    int4 dv = *(const int4*)(ei + Ee + e0);
    int ss4[4] = { sv.x, sv.y, sv.z, sv.w };
    int dd4[4] = { dv.x, dv.y, dv.z, dv.w };
#pragma unroll
    for (int i = 0; i < 4; i++) {
        int pos = atomicAdd(&g_cur[dd4[i]], 1);
        g_srcs[pos] = ss4[i];
    }
}

// ---------------- gather aggregation + alpha + normalize + pack -------------
// One 64-thread block per dst node. Staging threads gather ssrc[s] and
// compute alpha in fp32 (sdst is fixed per block); inner loop reads only
// smem + independent g_hf gathers.
__global__ void __launch_bounds__(64) k_agg() {
    __shared__ int   s_src[64];
    __shared__ float s_alp[64][4];
    int d = blockIdx.x;
    int j = threadIdx.x;             // 0..63 : float4 group within 256-row
    int h = j >> 4;
    int beg = g_off[d], cnt = g_cnt[d];
    float4 sd4 = *(const float4*)(g_sdst + d * 4);
    float4 acc = make_float4(0.f, 0.f, 0.f, 0.f);
    float asum = 0.f;
    for (int base = 0; base < cnt; base += 64) {
        int nb = min(64, cnt - base);
        if (j < nb) {
            int k = beg + base + j;
            int s = g_srcs[k];
            s_src[j] = s;
            float4 sv = *(const float4*)(g_ssrc + s * 4);
            s_alp[j][0] = __expf(leaky(sv.x + sd4.x));
            s_alp[j][1] = __expf(leaky(sv.y + sd4.y));
            s_alp[j][2] = __expf(leaky(sv.z + sd4.z));
            s_alp[j][3] = __expf(leaky(sv.w + sd4.w));
        }
        __syncthreads();
#pragma unroll 4
        for (int t = 0; t < nb; t++) {
            int s = s_src[t];
            float a = s_alp[t][h];
            const __half2* hp = (const __half2*)(g_hf + (long)s * HD + j * 4);
            float2 f0 = __half22float2(hp[0]);
            float2 f1 = __half22float2(hp[1]);
            asum += a;
            acc.x = fmaf(a, f0.x, acc.x);
            acc.y = fmaf(a, f0.y, acc.y);
            acc.z = fmaf(a, f1.x, acc.z);
            acc.w = fmaf(a, f1.y, acc.w);
        }
        __syncthreads();
    }
    float inv = 1.f / (asum + 1e-8f);
    float f[4] = { acc.x * inv, acc.y * inv, acc.z * inv, acc.w * inv };
    uint2 ph, pl;
    pack_split(f, ph, pl);
    long base2 = (long)d * KA + j * 4;
    *(uint2*)(g_o2 + base2)       = ph;
    *(uint2*)(g_o2 + base2 + 256) = pl;
}

// ---------------- launch ----------------------------------------------------
extern "C" void kernel_launch(void* const* d_in, const int* in_sizes, int n_in,
                              void* d_out, int out_size)
{
    const float* x    = (const float*)d_in[0];
    const int*   ei   = (const int*)  d_in[1];
    const float* W    = (const float*)d_in[2];
    const float* attn = (const float*)d_in[3];
    const float* Wout = (const float*)d_in[4];
    float*       out  = (float*)d_out;

    void *p_hf, *p_a2, *p_o2, *p_b1, *p_b2;
    cudaGetSymbolAddress(&p_hf, g_hf);
    cudaGetSymbolAddress(&p_a2, g_a2);
    cudaGetSymbolAddress(&p_o2, g_o2);
    cudaGetSymbolAddress(&p_b1, g_b1);
    cudaGetSymbolAddress(&p_b2, g_b2);

    cudaFuncSetAttribute(k_gemm_mma, cudaFuncAttributeMaxDynamicSharedMemorySize, 65536);

    int eb = (Ee + 255) / 256;

    k_init0<<<(NH + 255) / 256, 256>>>();
    k_hist<<<eb, 256>>>(ei);
    k_offs<<<(Nn + 255) / 256, 256>>>();
    k_edge_sort<<<(Ee / 4 + 255) / 256, 256>>>(ei);
    k_prep_w<<<256, 256>>>(W, Wout);
    k_prep_x<<<(Nn * 64 + 255) / 256, 256>>>(x);

    dim3 gg(2, (Nn + 127) / 128);           // n-tiles fast -> A shared via L2
    k_gemm_mma<<<gg, 256, 65536>>>((const __nv_bfloat16*)p_a2,
                                   (const __nv_bfloat16*)p_b1,
                                   (float*)nullptr, (__half*)p_hf, attn, Nn);

    k_agg<<<Nn, 64>>>();

    k_gemm_mma<<<gg, 256, 65536>>>((const __nv_bfloat16*)p_o2,
                                   (const __nv_bfloat16*)p_b2,
                                   out, (__half*)nullptr, (const float*)nullptr, Nn);
}

// round 11
// speedup vs baseline: 2.9874x; 1.1027x over previous
#include <cuda_runtime.h>
#include <cuda_bf16.h>
#include <cuda_fp16.h>
#include <math.h>
#include <stdint.h>

#define Nn   50000
#define Ee   1000000
#define Hh   4
#define Dd   64
#define NH   (Nn * Hh)   // 200000
#define HD   (Hh * Dd)   // 256
#define KA   512         // A storage: [Ah | Al]
#define KK   768         // B storage: [Bh | Bl | Bh]; virtual GEMM K

// ---------------- scratch (device globals; no allocation allowed) ----------
__device__ __half g_hf[Nn * HD];    // fp16 node features for the gather pass
__device__ float  g_ssrc[NH];
__device__ float  g_sdst[NH];
// CSR (dst-bucketed) edge structures
__device__ int    g_cnt[Nn];
__device__ int    g_off[Nn];
__device__ int    g_cur[Nn];
__device__ int    g_srcs[Ee];
__device__ int    g_total;          // global offset counter
// packed split-bf16 operands
__device__ __nv_bfloat16 g_a2[Nn * KA];    // [xh | xl]
__device__ __nv_bfloat16 g_o2[Nn * KA];    // normalized out_h packed [hi | lo]
__device__ __nv_bfloat16 g_b1[256 * KK];   // W  head-blocked, row n = out col
__device__ __nv_bfloat16 g_b2[256 * KK];   // W_out transposed

#define SWZ(o) ((o) ^ (((o) >> 3) & 0x70))

__device__ __forceinline__ uint32_t smem_u32(const void* p) {
    uint32_t a;
    asm("{ .reg .u64 t; cvta.to.shared.u64 t, %1; cvt.u32.u64 %0, t; }"
        : "=r"(a) : "l"(p));
    return a;
}
__device__ __forceinline__ void cp16(uint32_t dst, const void* src) {
    asm volatile("cp.async.cg.shared.global [%0], [%1], 16;"
                 :: "r"(dst), "l"(src) : "memory");
}
__device__ __forceinline__ void ldm_x4(uint32_t* r, uint32_t addr) {
    asm volatile("ldmatrix.sync.aligned.m8n8.x4.shared.b16 {%0,%1,%2,%3}, [%4];"
                 : "=r"(r[0]), "=r"(r[1]), "=r"(r[2]), "=r"(r[3]) : "r"(addr));
}
__device__ __forceinline__ void mma16816(float* c, const uint32_t* a,
                                         uint32_t b0, uint32_t b1) {
    asm volatile(
        "mma.sync.aligned.m16n8k16.row.col.f32.bf16.bf16.f32 "
        "{%0,%1,%2,%3}, {%4,%5,%6,%7}, {%8,%9}, {%0,%1,%2,%3};"
        : "+f"(c[0]), "+f"(c[1]), "+f"(c[2]), "+f"(c[3])
        : "r"(a[0]), "r"(a[1]), "r"(a[2]), "r"(a[3]), "r"(b0), "r"(b1));
}

// ---------------- init + CSR build ------------------------------------------
__global__ void k_init0() {
    int i = blockIdx.x * blockDim.x + threadIdx.x;
    if (i == 0) g_total = 0;
    if (i < Nn) g_cnt[i] = 0;
    if (i < NH) { g_ssrc[i] = 0.f; g_sdst[i] = 0.f; }
}
__global__ void k_hist(const int* __restrict__ ei) {
    int e = blockIdx.x * blockDim.x + threadIdx.x;
    if (e < Ee) atomicAdd(&g_cnt[ei[Ee + e]], 1);
}
// parallel offsets: warp-scan + one global atomic per warp. Offsets are
// disjoint ranges (order across warps is arbitrary — CSR doesn't care).
__global__ void k_offs() {
    int i = blockIdx.x * blockDim.x + threadIdx.x;
    int lane = threadIdx.x & 31;
    int c = (i < Nn) ? g_cnt[i] : 0;
    int incl = c;
#pragma unroll
    for (int o = 1; o < 32; o <<= 1) {
        int v = __shfl_up_sync(0xFFFFFFFFu, incl, o);
        if (lane >= o) incl += v;
    }
    int total = __shfl_sync(0xFFFFFFFFu, incl, 31);
    int base = 0;
    if (lane == 31) base = atomicAdd(&g_total, total);
    base = __shfl_sync(0xFFFFFFFFu, base, 31);
    int off = base + incl - c;
    if (i < Nn) { g_off[i] = off; g_cur[i] = off; }
}

// ---------------- edge pass: pure permutation build --------------------------
__global__ void k_edge_sort(const int* __restrict__ ei) {
    int t = blockIdx.x * blockDim.x + threadIdx.x;
    int e0 = t * 4;
    if (e0 >= Ee) return;
    int4 sv = *(const int4*)(ei + e0);
    int4 dv = *(const int4*)(ei + Ee + e0);
    int ss4[4] = { sv.x, sv.y, sv.z, sv.w };
    int dd4[4] = { dv.x, dv.y, dv.z, dv.w };
#pragma unroll
    for (int i = 0; i < 4; i++) {
        int pos = atomicAdd(&g_cur[dd4[i]], 1);
        g_srcs[pos] = ss4[i];
    }
}

// ---------------- pack fp32 -> [hi | lo] bf16 -------------------------------
__device__ __forceinline__ void pack_split(const float* f, uint2& ph, uint2& pl) {
    unsigned short hs[4], ls[4];
#pragma unroll
    for (int i = 0; i < 4; i++) {
        __nv_bfloat16 h = __float2bfloat16(f[i]);
        __nv_bfloat16 l = __float2bfloat16(f[i] - __bfloat162float(h));
        hs[i] = __bfloat16_as_ushort(h);
        ls[i] = __bfloat16_as_ushort(l);
    }
    ph = make_uint2((uint32_t)hs[0] | ((uint32_t)hs[1] << 16),
                    (uint32_t)hs[2] | ((uint32_t)hs[3] << 16));
    pl = make_uint2((uint32_t)ls[0] | ((uint32_t)ls[1] << 16),
                    (uint32_t)ls[2] | ((uint32_t)ls[3] << 16));
}

// ---------------- merged prep: weights (blocks 0..255) + x (rest) -----------
__global__ void k_prep(const float* __restrict__ W, const float* __restrict__ Wout,
                       const float* __restrict__ x) {
    if (blockIdx.x < 256) {
        int t = blockIdx.x * 256 + threadIdx.x;   // 65536
        int n = t >> 8, k = t & 255;
        float v1 = W[(((n >> 6) * 256) + k) * 64 + (n & 63)];
        __nv_bfloat16 h1 = __float2bfloat16(v1);
        __nv_bfloat16 l1 = __float2bfloat16(v1 - __bfloat162float(h1));
        g_b1[n * KK + k]       = h1;
        g_b1[n * KK + 256 + k] = l1;
        g_b1[n * KK + 512 + k] = h1;
        float v2 = Wout[k * 256 + n];
        __nv_bfloat16 h2 = __float2bfloat16(v2);
        __nv_bfloat16 l2 = __float2bfloat16(v2 - __bfloat162float(h2));
        g_b2[n * KK + k]       = h2;
        g_b2[n * KK + 256 + k] = l2;
        g_b2[n * KK + 512 + k] = h2;
    } else {
        int t = (blockIdx.x - 256) * 256 + threadIdx.x;   // per float4
        if (t >= Nn * 64) return;
        float4 v = ((const float4*)x)[t];
        float f[4] = { v.x, v.y, v.z, v.w };
        uint2 ph, pl;
        pack_split(f, ph, pl);
        long base = (long)(t >> 6) * KA + (t & 63) * 4;
        *(uint2*)(g_a2 + base)       = ph;
        *(uint2*)(g_a2 + base + 256) = pl;
    }
}

// ---------------- bf16 mma.sync GEMM ----------------------------------------
// C[M,256] = A[M,512:(hi|lo)] x B[256,768:(Bh|Bl|Bh)]^T over virtual K=768.
// C may be nullptr; Chalf optional fp16 copy; attnp != nullptr fuses the
// attention-score reduction into the epilogue.
__global__ void __launch_bounds__(256) k_gemm_mma(
    const __nv_bfloat16* __restrict__ A, const __nv_bfloat16* __restrict__ B,
    float* __restrict__ C, __half* __restrict__ Chalf,
    const float* __restrict__ attnp, int M)
{
    extern __shared__ char sm[];
    uint32_t sbase = smem_u32(sm);
    const int tid = threadIdx.x;
    const int wid = tid >> 5, lid = tid & 31;
    const int bm = blockIdx.y * 128, bn = blockIdx.x * 128;
    const int wm = (wid >> 2) * 64, wn = (wid & 3) * 32;

    const int arow = (lid & 7) + ((lid >> 3) & 1) * 8;
    const int acol = (lid >> 4) * 8;
    const int q = lid >> 3;
    const int brow = (lid & 7) + (q >> 1) * 8;
    const int bcol = (q & 1) * 8;

    float acc[4][4][4];
#pragma unroll
    for (int mi = 0; mi < 4; mi++)
#pragma unroll
        for (int ni = 0; ni < 4; ni++)
#pragma unroll
            for (int j = 0; j < 4; j++) acc[mi][ni][j] = 0.f;

    auto load_chunk = [&](int c, int s) {
        uint32_t abase = sbase + s * 32768;
        int aoff = (c & 3) * 64 + ((c >= 8) ? 256 : 0);
#pragma unroll
        for (int it = 0; it < 4; it++) {
            int idx = tid + it * 256;
            int row = idx >> 3, col = (idx & 7) * 8;
            long ar = bm + row; if (ar >= M) ar = M - 1;
            cp16(abase + SWZ(row * 128 + col * 2), A + ar * KA + aoff + col);
        }
#pragma unroll
        for (int it = 0; it < 4; it++) {
            int idx = tid + it * 256;
            int row = idx >> 3, col = (idx & 7) * 8;
            cp16(abase + 16384 + SWZ(row * 128 + col * 2),
                 B + (long)(bn + row) * KK + c * 64 + col);
        }
        asm volatile("cp.async.commit_group;" ::: "memory");
    };

    auto compute_chunk = [&](int s) {
        uint32_t abase = sbase + s * 32768;
        uint32_t bbase = abase + 16384;
#pragma unroll
        for (int ks = 0; ks < 4; ks++) {
            uint32_t a[4][4];
#pragma unroll
            for (int mi = 0; mi < 4; mi++)
                ldm_x4(a[mi], abase + SWZ((wm + mi * 16 + arow) * 128 +
                                          (ks * 16 + acol) * 2));
            uint32_t b[2][4];
#pragma unroll
            for (int nj = 0; nj < 2; nj++)
                ldm_x4(b[nj], bbase + SWZ((wn + nj * 16 + brow) * 128 +
                                          (ks * 16 + bcol) * 2));
#pragma unroll
            for (int mi = 0; mi < 4; mi++)
#pragma unroll
                for (int ni = 0; ni < 4; ni++)
                    mma16816(acc[mi][ni], a[mi],
                             b[ni >> 1][(ni & 1) * 2], b[ni >> 1][(ni & 1) * 2 + 1]);
        }
    };

    load_chunk(0, 0);
    const int NC = 12;
    for (int c = 0; c < NC; c++) {
        if (c + 1 < NC) {
            load_chunk(c + 1, (c + 1) & 1);
            asm volatile("cp.async.wait_group 1;" ::: "memory");
        } else {
            asm volatile("cp.async.wait_group 0;" ::: "memory");
        }
        __syncthreads();
        compute_chunk(c & 1);
        __syncthreads();
    }

    const int g = lid >> 2, tig = lid & 3;

#pragma unroll
    for (int mi = 0; mi < 4; mi++) {
        int r0 = bm + wm + mi * 16 + g;
#pragma unroll
        for (int ni = 0; ni < 4; ni++) {
            int col = bn + wn + ni * 8 + tig * 2;
#pragma unroll
            for (int h2 = 0; h2 < 2; h2++) {
                int r = r0 + h2 * 8;
                if (r < M) {
                    float c0 = acc[mi][ni][h2 * 2];
                    float c1 = acc[mi][ni][h2 * 2 + 1];
                    if (C)
                        *(float2*)(C + (long)r * 256 + col) = make_float2(c0, c1);
                    if (Chalf)
                        *(__half2*)(Chalf + (long)r * 256 + col) =
                            __floats2half2_rn(c0, c1);
                }
            }
        }
    }

    // fused attention-score reduction (GEMM1 only)
    if (attnp) {
        int hh = ((bn + wn) >> 6) & 3;
        int dbase = (bn + wn) & 63;
        float as[8], ad[8];
#pragma unroll
        for (int ni = 0; ni < 4; ni++)
#pragma unroll
            for (int c2 = 0; c2 < 2; c2++) {
                int dd = dbase + ni * 8 + tig * 2 + c2;
                as[ni * 2 + c2] = __ldg(attnp + hh * 128 + dd);
                ad[ni * 2 + c2] = __ldg(attnp + hh * 128 + 64 + dd);
            }
#pragma unroll
        for (int mi = 0; mi < 4; mi++)
#pragma unroll
            for (int h2 = 0; h2 < 2; h2++) {
                int r = bm + wm + mi * 16 + g + h2 * 8;
                if (r < M) {
                    float ps = 0.f, pd = 0.f;
#pragma unroll
                    for (int ni = 0; ni < 4; ni++) {
                        float c0 = acc[mi][ni][h2 * 2];
                        float c1 = acc[mi][ni][h2 * 2 + 1];
                        ps += c0 * as[ni * 2] + c1 * as[ni * 2 + 1];
                        pd += c0 * ad[ni * 2] + c1 * ad[ni * 2 + 1];
                    }
                    atomicAdd(&g_ssrc[r * 4 + hh], ps);
                    atomicAdd(&g_sdst[r * 4 + hh], pd);
                }
            }
    }
}

__device__ __forceinline__ float leaky(float v) {
    return v > 0.f ? v : 0.2f * v;
}

// ---------------- gather aggregation + alpha + normalize + pack -------------
__global__ void __launch_bounds__(64) k_agg() {
    __shared__ int   s_src[64];
    __shared__ float s_alp[64][4];
    int d = blockIdx.x;
    int j = threadIdx.x;             // 0..63 : float4 group within 256-row
    int h = j >> 4;
    int beg = g_off[d], cnt = g_cnt[d];
    float4 sd4 = *(const float4*)(g_sdst + d * 4);
    float4 acc = make_float4(0.f, 0.f, 0.f, 0.f);
    float asum = 0.f;
    for (int base = 0; base < cnt; base += 64) {
        int nb = min(64, cnt - base);
        if (j < nb) {
            int k = beg + base + j;
            int s = g_srcs[k];
            s_src[j] = s;
            float4 sv = *(const float4*)(g_ssrc + s * 4);
            s_alp[j][0] = __expf(leaky(sv.x + sd4.x));
            s_alp[j][1] = __expf(leaky(sv.y + sd4.y));
            s_alp[j][2] = __expf(leaky(sv.z + sd4.z));
            s_alp[j][3] = __expf(leaky(sv.w + sd4.w));
        }
        __syncthreads();
#pragma unroll 4
        for (int t = 0; t < nb; t++) {
            int s = s_src[t];
            float a = s_alp[t][h];
            const __half2* hp = (const __half2*)(g_hf + (long)s * HD + j * 4);
            float2 f0 = __half22float2(hp[0]);
            float2 f1 = __half22float2(hp[1]);
            asum += a;
            acc.x = fmaf(a, f0.x, acc.x);
            acc.y = fmaf(a, f0.y, acc.y);
            acc.z = fmaf(a, f1.x, acc.z);
            acc.w = fmaf(a, f1.y, acc.w);
        }
        __syncthreads();
    }
    float inv = 1.f / (asum + 1e-8f);
    float f[4] = { acc.x * inv, acc.y * inv, acc.z * inv, acc.w * inv };
    uint2 ph, pl;
    pack_split(f, ph, pl);
    long base2 = (long)d * KA + j * 4;
    *(uint2*)(g_o2 + base2)       = ph;
    *(uint2*)(g_o2 + base2 + 256) = pl;
}

// ---------------- launch ----------------------------------------------------
extern "C" void kernel_launch(void* const* d_in, const int* in_sizes, int n_in,
                              void* d_out, int out_size)
{
    const float* x    = (const float*)d_in[0];
    const int*   ei   = (const int*)  d_in[1];
    const float* W    = (const float*)d_in[2];
    const float* attn = (const float*)d_in[3];
    const float* Wout = (const float*)d_in[4];
    float*       out  = (float*)d_out;

    void *p_hf, *p_a2, *p_o2, *p_b1, *p_b2;
    cudaGetSymbolAddress(&p_hf, g_hf);
    cudaGetSymbolAddress(&p_a2, g_a2);
    cudaGetSymbolAddress(&p_o2, g_o2);
    cudaGetSymbolAddress(&p_b1, g_b1);
    cudaGetSymbolAddress(&p_b2, g_b2);

    cudaFuncSetAttribute(k_gemm_mma, cudaFuncAttributeMaxDynamicSharedMemorySize, 65536);

    // side stream for the CSR-build chain (capture-safe fork/join).
    cudaStream_t s1;
    cudaStreamCreateWithFlags(&s1, cudaStreamNonBlocking);
    cudaEvent_t e0, e1;
    cudaEventCreateWithFlags(&e0, cudaEventDisableTiming);
    cudaEventCreateWithFlags(&e1, cudaEventDisableTiming);

    int eb = (Ee + 255) / 256;

    k_init0<<<(NH + 255) / 256, 256>>>();

    // fork: CSR build (hist -> offs -> edge_sort) on s1
    cudaEventRecord(e0, 0);
    cudaStreamWaitEvent(s1, e0, 0);
    k_hist<<<eb, 256, 0, s1>>>(ei);
    k_offs<<<(Nn + 255) / 256, 256, 0, s1>>>();
    k_edge_sort<<<(Ee / 4 + 255) / 256, 256, 0, s1>>>(ei);
    cudaEventRecord(e1, s1);

    // main stream: prep + GEMM1 (independent of CSR build)
    k_prep<<<256 + (Nn * 64 + 255) / 256, 256>>>(W, Wout, x);

    dim3 gg(2, (Nn + 127) / 128);           // n-tiles fast -> A shared via L2
    k_gemm_mma<<<gg, 256, 65536>>>((const __nv_bfloat16*)p_a2,
                                   (const __nv_bfloat16*)p_b1,
                                   (float*)nullptr, (__half*)p_hf, attn, Nn);

    // join: agg needs both GEMM1 results and the CSR permutation
    cudaStreamWaitEvent(0, e1, 0);

    k_agg<<<Nn, 64>>>();

    k_gemm_mma<<<gg, 256, 65536>>>((const __nv_bfloat16*)p_o2,
                                   (const __nv_bfloat16*)p_b2,
                                   out, (__half*)nullptr, (const float*)nullptr, Nn);
}